// round 15
// baseline (speedup 1.0000x reference)
#include <cuda_runtime.h>
#include <cuda_bf16.h>

// Problem constants
#define CB 8
#define CQ 900
#define CD 256
#define CNH 8
#define CDH 32
#define CFF 1024
#define CS 13294          // 100*100 + 50*50 + 25*25 + 13*13
#define CBQ (CB*CQ)       // 7200
#define CBS (CB*CS)       // 106352
#define CNLAYERS 6
#define ATTN_SCALE 0.17677669529663687f   // 1/sqrt(32)

// ------------------------- scratch (device globals) -------------------------
__device__ float g_value[CBS*CD];     // projected value, layer-invariant
__device__ float g_x    [CBQ*CD];     // decoder state
__device__ float g_xpq  [CBQ*CD];     // x + query_pos
__device__ float g_qkv  [CBQ*3*CD];
__device__ float g_attn [CBQ*CD];
__device__ float g_t2   [CBQ*CD];
__device__ float g_offaw[CBQ*384];    // fused sampling offsets (256) + aw logits (128)
__device__ float g_ms   [CBQ*CD];     // msda gather output
__device__ float g_ffh  [CBQ*CFF];    // ffn hidden
__device__ float g_sob  [384];        // concatenated so_b | aw_b

// split-weight planes (packed bf16 pairs along K). offsets in uint32 pairs.
#define OFF_VP   0
#define OFF_SAIN (OFF_VP   + 32768)    // vp:   256*256/2
#define OFF_SAOU (OFF_SAIN + 98304)    // sain: 768*256/2
#define OFF_SO   (OFF_SAOU + 32768)    // so+aw combined: 384*256/2
#define OFF_AW   (OFF_SO   + 32768)    // aw block lives right after so block
#define OFF_OP   (OFF_AW   + 16384)
#define OFF_FF1  (OFF_OP   + 32768)
#define OFF_FF2  (OFF_FF1  + 131072)
#define WSPLIT_TOTAL (OFF_FF2 + 131072) // 507904
__device__ unsigned g_wh[WSPLIT_TOTAL];
__device__ unsigned g_wl[WSPLIT_TOTAL];

// ------------------------- bf16 split helpers -------------------------
__device__ __forceinline__ void split2(float x, float y, unsigned& hi, unsigned& lo) {
    __nv_bfloat162 h = __floats2bfloat162_rn(x, y);
    hi = *reinterpret_cast<unsigned*>(&h);
    float rx = x - __bfloat162float(h.x);
    float ry = y - __bfloat162float(h.y);
    __nv_bfloat162 l = __floats2bfloat162_rn(rx, ry);
    lo = *reinterpret_cast<unsigned*>(&l);
}

__device__ __forceinline__ void mma_bf16(float* d, const unsigned* a, unsigned b0, unsigned b1) {
    asm volatile(
        "mma.sync.aligned.m16n8k16.row.col.f32.bf16.bf16.f32 "
        "{%0,%1,%2,%3}, {%4,%5,%6,%7}, {%8,%9}, {%0,%1,%2,%3};"
        : "+f"(d[0]), "+f"(d[1]), "+f"(d[2]), "+f"(d[3])
        : "r"(a[0]), "r"(a[1]), "r"(a[2]), "r"(a[3]), "r"(b0), "r"(b1));
}

// ------------------------- fused prologue: weight split + xpq add + refs + bias concat -------------------------
#define PRO_XPQ  (WSPLIT_TOTAL)                 // xpq = tgt + qpos : CBQ*CD elems
#define PRO_REFS (PRO_XPQ + CBQ*CD)             // write_refs      : CBQ*2 elems
#define PRO_SOB  (PRO_REFS + CB*CQ*2)           // sob concat      : 384 elems
#define PRO_TOTAL (PRO_SOB + 384)
__global__ void prologue_kernel(const float* __restrict__ vp,  const float* __restrict__ sain,
                                const float* __restrict__ saou,const float* __restrict__ so,
                                const float* __restrict__ aw,  const float* __restrict__ op,
                                const float* __restrict__ ff1, const float* __restrict__ ff2,
                                unsigned* __restrict__ wh, unsigned* __restrict__ wl,
                                const float* __restrict__ tgt, const float* __restrict__ qpos,
                                float* __restrict__ xpq,
                                const float* __restrict__ refp, float* __restrict__ outrefs,
                                const float* __restrict__ so_b, const float* __restrict__ aw_b,
                                float* __restrict__ sob) {
    int i = blockIdx.x * blockDim.x + threadIdx.x;
    if (i < WSPLIT_TOTAL) {
        const float* src; int off;
        if      (i < OFF_SAIN) { src = vp;   off = i - OFF_VP;   }
        else if (i < OFF_SAOU) { src = sain; off = i - OFF_SAIN; }
        else if (i < OFF_SO)   { src = saou; off = i - OFF_SAOU; }
        else if (i < OFF_AW)   { src = so;   off = i - OFF_SO;   }
        else if (i < OFF_OP)   { src = aw;   off = i - OFF_AW;   }
        else if (i < OFF_FF1)  { src = op;   off = i - OFF_OP;   }
        else if (i < OFF_FF2)  { src = ff1;  off = i - OFF_FF1;  }
        else                   { src = ff2;  off = i - OFF_FF2;  }
        unsigned h, l;
        split2(src[2*off], src[2*off+1], h, l);
        wh[i] = h; wl[i] = l;
    } else if (i < PRO_REFS) {
        int j = i - PRO_XPQ;
        xpq[j] = tgt[j] + qpos[j];
    } else if (i < PRO_SOB) {
        int j = i - PRO_REFS;
        float v = refp[j];
        const int n = CB * CQ * 2;
        #pragma unroll
        for (int L = 0; L < CNLAYERS; L++) outrefs[(size_t)L * n + j] = v;
    } else if (i < PRO_TOTAL) {
        int j = i - PRO_SOB;
        sob[j] = (j < 256) ? so_b[j] : aw_b[j - 256];
    }
}

// ------------------------- bf16x3 tensor-core GEMM (128x128 tile, K compile-time) -------------------------
template<bool RELU, int K>
__global__ __launch_bounds__(256)
void gemm_bf3(const float* __restrict__ A, const unsigned* __restrict__ Wh,
              const unsigned* __restrict__ Wl, const float* __restrict__ bias,
              float* __restrict__ C, int M, int N) {
    __shared__ unsigned Ah[128][20];
    __shared__ unsigned Al[128][20];
    __shared__ unsigned Bh[128][20];
    __shared__ unsigned Bl[128][20];

    const int tid  = threadIdx.x;
    const int lane = tid & 31, warp = tid >> 5;
    const int g = lane >> 2, tg = lane & 3;
    const int warpM = warp & 1, warpN = warp >> 1;   // 2 x 4 warps
    const int m0 = warpM * 64, n0 = warpN * 32;
    const int rowBase = blockIdx.y * 128, colBase = blockIdx.x * 128;
    constexpr int Kp = K >> 1;

    const int lrow  = tid >> 1;
    const int lhalf = tid & 1;
    const int kpb   = lhalf * 8;
    const int arow  = rowBase + lrow;
    const bool av   = arow < M;
    const float*    ap  = A  + (size_t)arow * K + lhalf * 16;
    const unsigned* bhp = Wh + (size_t)(colBase + lrow) * Kp + kpb;
    const unsigned* blp = Wl + (size_t)(colBase + lrow) * Kp + kpb;

    float acc[4][4][4];
    #pragma unroll
    for (int i = 0; i < 4; i++)
        #pragma unroll
        for (int j = 0; j < 4; j++)
            #pragma unroll
            for (int r = 0; r < 4; r++) acc[i][j][r] = 0.f;

    const float4 fz = make_float4(0.f, 0.f, 0.f, 0.f);
    float4 ra[4]; uint4 rbh[2], rbl[2];
    #pragma unroll
    for (int j = 0; j < 4; j++) ra[j] = av ? *(const float4*)(ap + 4*j) : fz;
    rbh[0] = *(const uint4*)(bhp);     rbh[1] = *(const uint4*)(bhp + 4);
    rbl[0] = *(const uint4*)(blp);     rbl[1] = *(const uint4*)(blp + 4);

    constexpr int ntiles = K >> 5;
    #pragma unroll
    for (int kt = 0; kt < ntiles; kt++) {
        #pragma unroll
        for (int j = 0; j < 4; j++) {
            unsigned h0, l0, h1, l1;
            split2(ra[j].x, ra[j].y, h0, l0);
            split2(ra[j].z, ra[j].w, h1, l1);
            Ah[lrow][kpb + 2*j]     = h0;  Ah[lrow][kpb + 2*j + 1] = h1;
            Al[lrow][kpb + 2*j]     = l0;  Al[lrow][kpb + 2*j + 1] = l1;
        }
        Bh[lrow][kpb+0] = rbh[0].x; Bh[lrow][kpb+1] = rbh[0].y;
        Bh[lrow][kpb+2] = rbh[0].z; Bh[lrow][kpb+3] = rbh[0].w;
        Bh[lrow][kpb+4] = rbh[1].x; Bh[lrow][kpb+5] = rbh[1].y;
        Bh[lrow][kpb+6] = rbh[1].z; Bh[lrow][kpb+7] = rbh[1].w;
        Bl[lrow][kpb+0] = rbl[0].x; Bl[lrow][kpb+1] = rbl[0].y;
        Bl[lrow][kpb+2] = rbl[0].z; Bl[lrow][kpb+3] = rbl[0].w;
        Bl[lrow][kpb+4] = rbl[1].x; Bl[lrow][kpb+5] = rbl[1].y;
        Bl[lrow][kpb+6] = rbl[1].z; Bl[lrow][kpb+7] = rbl[1].w;
        __syncthreads();

        if (kt + 1 < ntiles) {
            const int fo = (kt + 1) * 32;
            const int po = (kt + 1) * 16;
            #pragma unroll
            for (int j = 0; j < 4; j++) ra[j] = av ? *(const float4*)(ap + fo + 4*j) : fz;
            rbh[0] = *(const uint4*)(bhp + po); rbh[1] = *(const uint4*)(bhp + po + 4);
            rbl[0] = *(const uint4*)(blp + po); rbl[1] = *(const uint4*)(blp + po + 4);
        }

        #pragma unroll
        for (int ks = 0; ks < 2; ks++) {
            const int kq = ks * 8 + tg;
            unsigned af[4][4], alf[4][4];
            #pragma unroll
            for (int mt = 0; mt < 4; mt++) {
                const int mm = m0 + mt * 16 + g;
                af[mt][0]  = Ah[mm][kq];   af[mt][1]  = Ah[mm+8][kq];
                af[mt][2]  = Ah[mm][kq+4]; af[mt][3]  = Ah[mm+8][kq+4];
                alf[mt][0] = Al[mm][kq];   alf[mt][1] = Al[mm+8][kq];
                alf[mt][2] = Al[mm][kq+4]; alf[mt][3] = Al[mm+8][kq+4];
            }
            #pragma unroll
            for (int nt = 0; nt < 4; nt++) {
                const int nn = n0 + nt * 8 + g;
                const unsigned bh0 = Bh[nn][kq], bh1 = Bh[nn][kq+4];
                const unsigned bl0 = Bl[nn][kq], bl1 = Bl[nn][kq+4];
                #pragma unroll
                for (int mt = 0; mt < 4; mt++) mma_bf16(acc[mt][nt], alf[mt], bh0, bh1);
                #pragma unroll
                for (int mt = 0; mt < 4; mt++) mma_bf16(acc[mt][nt], af[mt],  bl0, bl1);
                #pragma unroll
                for (int mt = 0; mt < 4; mt++) mma_bf16(acc[mt][nt], af[mt],  bh0, bh1);
            }
        }
        __syncthreads();
    }

    #pragma unroll
    for (int mt = 0; mt < 4; mt++) {
        const int m  = rowBase + m0 + mt * 16 + g;
        #pragma unroll
        for (int nt = 0; nt < 4; nt++) {
            const int n = colBase + n0 + nt * 8 + 2 * tg;
            const float2 bv = *(const float2*)&bias[n];
            float* c = acc[mt][nt];
            if (m < M) {
                float2 o0 = make_float2(c[0] + bv.x, c[1] + bv.y);
                if (RELU) { o0.x = fmaxf(o0.x, 0.f); o0.y = fmaxf(o0.y, 0.f); }
                *(float2*)&C[(size_t)m * N + n] = o0;
            }
            if (m + 8 < M) {
                float2 o1 = make_float2(c[2] + bv.x, c[3] + bv.y);
                if (RELU) { o1.x = fmaxf(o1.x, 0.f); o1.y = fmaxf(o1.y, 0.f); }
                *(float2*)&C[(size_t)(m + 8) * N + n] = o1;
            }
        }
    }
}

// ------------------------- bf16x3 GEMM, 64x128 tile (for narrow-N outputs) -------------------------
template<int K>
__global__ __launch_bounds__(256)
void gemm_bf3_m64(const float* __restrict__ A, const unsigned* __restrict__ Wh,
                  const unsigned* __restrict__ Wl, const float* __restrict__ bias,
                  float* __restrict__ C, int M, int N) {
    __shared__ unsigned Ah[64][20];
    __shared__ unsigned Al[64][20];
    __shared__ unsigned Bh[128][20];
    __shared__ unsigned Bl[128][20];

    const int tid  = threadIdx.x;
    const int lane = tid & 31, warp = tid >> 5;
    const int g = lane >> 2, tg = lane & 3;
    const int warpM = warp & 1, warpN = warp >> 1;   // 2 x 4 warps
    const int m0 = warpM * 32, n0 = warpN * 32;
    const int rowBase = blockIdx.y * 64, colBase = blockIdx.x * 128;
    constexpr int Kp = K >> 1;

    const int arow = tid >> 2, aq = tid & 3;
    const int kpa  = aq * 4;
    const int garow = rowBase + arow;
    const bool av   = garow < M;
    const float* ap = A + (size_t)garow * K + aq * 8;

    const int lrow  = tid >> 1;
    const int lhalf = tid & 1;
    const int kpb   = lhalf * 8;
    const unsigned* bhp = Wh + (size_t)(colBase + lrow) * Kp + kpb;
    const unsigned* blp = Wl + (size_t)(colBase + lrow) * Kp + kpb;

    float acc[2][4][4];
    #pragma unroll
    for (int i = 0; i < 2; i++)
        #pragma unroll
        for (int j = 0; j < 4; j++)
            #pragma unroll
            for (int r = 0; r < 4; r++) acc[i][j][r] = 0.f;

    const float4 fz = make_float4(0.f, 0.f, 0.f, 0.f);
    float4 ra[2]; uint4 rbh[2], rbl[2];
    ra[0] = av ? *(const float4*)ap       : fz;
    ra[1] = av ? *(const float4*)(ap + 4) : fz;
    rbh[0] = *(const uint4*)(bhp);     rbh[1] = *(const uint4*)(bhp + 4);
    rbl[0] = *(const uint4*)(blp);     rbl[1] = *(const uint4*)(blp + 4);

    constexpr int ntiles = K >> 5;
    #pragma unroll
    for (int kt = 0; kt < ntiles; kt++) {
        {
            unsigned h0, l0, h1, l1;
            split2(ra[0].x, ra[0].y, h0, l0);
            split2(ra[0].z, ra[0].w, h1, l1);
            Ah[arow][kpa+0] = h0;  Ah[arow][kpa+1] = h1;
            Al[arow][kpa+0] = l0;  Al[arow][kpa+1] = l1;
            split2(ra[1].x, ra[1].y, h0, l0);
            split2(ra[1].z, ra[1].w, h1, l1);
            Ah[arow][kpa+2] = h0;  Ah[arow][kpa+3] = h1;
            Al[arow][kpa+2] = l0;  Al[arow][kpa+3] = l1;
        }
        Bh[lrow][kpb+0] = rbh[0].x; Bh[lrow][kpb+1] = rbh[0].y;
        Bh[lrow][kpb+2] = rbh[0].z; Bh[lrow][kpb+3] = rbh[0].w;
        Bh[lrow][kpb+4] = rbh[1].x; Bh[lrow][kpb+5] = rbh[1].y;
        Bh[lrow][kpb+6] = rbh[1].z; Bh[lrow][kpb+7] = rbh[1].w;
        Bl[lrow][kpb+0] = rbl[0].x; Bl[lrow][kpb+1] = rbl[0].y;
        Bl[lrow][kpb+2] = rbl[0].z; Bl[lrow][kpb+3] = rbl[0].w;
        Bl[lrow][kpb+4] = rbl[1].x; Bl[lrow][kpb+5] = rbl[1].y;
        Bl[lrow][kpb+6] = rbl[1].z; Bl[lrow][kpb+7] = rbl[1].w;
        __syncthreads();

        if (kt + 1 < ntiles) {
            const int fo = (kt + 1) * 32;
            const int po = (kt + 1) * 16;
            ra[0] = av ? *(const float4*)(ap + fo)     : fz;
            ra[1] = av ? *(const float4*)(ap + fo + 4) : fz;
            rbh[0] = *(const uint4*)(bhp + po); rbh[1] = *(const uint4*)(bhp + po + 4);
            rbl[0] = *(const uint4*)(blp + po); rbl[1] = *(const uint4*)(blp + po + 4);
        }

        #pragma unroll
        for (int ks = 0; ks < 2; ks++) {
            const int kq = ks * 8 + tg;
            unsigned af[2][4], alf[2][4];
            #pragma unroll
            for (int mt = 0; mt < 2; mt++) {
                const int mm = m0 + mt * 16 + g;
                af[mt][0]  = Ah[mm][kq];   af[mt][1]  = Ah[mm+8][kq];
                af[mt][2]  = Ah[mm][kq+4]; af[mt][3]  = Ah[mm+8][kq+4];
                alf[mt][0] = Al[mm][kq];   alf[mt][1] = Al[mm+8][kq];
                alf[mt][2] = Al[mm][kq+4]; alf[mt][3] = Al[mm+8][kq+4];
            }
            #pragma unroll
            for (int nt = 0; nt < 4; nt++) {
                const int nn = n0 + nt * 8 + g;
                const unsigned bh0 = Bh[nn][kq], bh1 = Bh[nn][kq+4];
                const unsigned bl0 = Bl[nn][kq], bl1 = Bl[nn][kq+4];
                #pragma unroll
                for (int mt = 0; mt < 2; mt++) mma_bf16(acc[mt][nt], alf[mt], bh0, bh1);
                #pragma unroll
                for (int mt = 0; mt < 2; mt++) mma_bf16(acc[mt][nt], af[mt],  bl0, bl1);
                #pragma unroll
                for (int mt = 0; mt < 2; mt++) mma_bf16(acc[mt][nt], af[mt],  bh0, bh1);
            }
        }
        __syncthreads();
    }

    #pragma unroll
    for (int mt = 0; mt < 2; mt++) {
        const int m  = rowBase + m0 + mt * 16 + g;
        #pragma unroll
        for (int nt = 0; nt < 4; nt++) {
            const int n = colBase + n0 + nt * 8 + 2 * tg;
            const float2 bv = *(const float2*)&bias[n];
            float* c = acc[mt][nt];
            if (m < M) {
                *(float2*)&C[(size_t)m * N + n] = make_float2(c[0] + bv.x, c[1] + bv.y);
            }
            if (m + 8 < M) {
                *(float2*)&C[(size_t)(m + 8) * N + n] = make_float2(c[2] + bv.x, c[3] + bv.y);
            }
        }
    }
}

// ------------------------- tensor-core flash attention (q-tile 128, 8 warps, 3 CTAs/SM) -------------------------
__global__ __launch_bounds__(256, 3)
void flash_attn_tc(const float* __restrict__ qkv, float* __restrict__ out) {
    const int qt = blockIdx.x, h = blockIdx.y, b = blockIdx.z;
    const int t = threadIdx.x, lane = t & 31, warp = t >> 5;
    const int g = lane >> 2, tg = lane & 3;

    __shared__ unsigned Qh[128][20], Ql[128][20];
    __shared__ unsigned Kh[64][20],  Kl[64][20];
    __shared__ unsigned VTh[32][36], VTl[32][36];

    const int q0 = qt * 128;
    const size_t basebq = (size_t)b * CQ;
    const int r = t >> 1, half = t & 1;          // Q loader: 2 threads/row over 128 rows

    // ---- load Q tile (pre-scaled), split hi/lo ----
    {
        const int gq = q0 + r;
        float4 v[4];
        if (gq < CQ) {
            const float* p = qkv + (basebq + gq) * 768 + h * CDH + half * 16;
            #pragma unroll
            for (int j = 0; j < 4; j++) v[j] = *(const float4*)(p + 4*j);
        } else {
            #pragma unroll
            for (int j = 0; j < 4; j++) v[j] = make_float4(0.f,0.f,0.f,0.f);
        }
        #pragma unroll
        for (int j = 0; j < 4; j++) {
            unsigned h0, l0, h1, l1;
            split2(v[j].x * ATTN_SCALE, v[j].y * ATTN_SCALE, h0, l0);
            split2(v[j].z * ATTN_SCALE, v[j].w * ATTN_SCALE, h1, l1);
            Qh[r][half*8 + 2*j]     = h0;  Qh[r][half*8 + 2*j + 1] = h1;
            Ql[r][half*8 + 2*j]     = l0;  Ql[r][half*8 + 2*j + 1] = l1;
        }
    }
    __syncthreads();

    // Q fragments (persist across k-tiles); warp owns rows m0..m0+15
    unsigned qh[2][4], ql[2][4];
    const int m0 = warp * 16;
    #pragma unroll
    for (int kc = 0; kc < 2; kc++) {
        const int kq = kc * 8 + tg;
        qh[kc][0] = Qh[m0+g][kq];   qh[kc][1] = Qh[m0+g+8][kq];
        qh[kc][2] = Qh[m0+g][kq+4]; qh[kc][3] = Qh[m0+g+8][kq+4];
        ql[kc][0] = Ql[m0+g][kq];   ql[kc][1] = Ql[m0+g+8][kq];
        ql[kc][2] = Ql[m0+g][kq+4]; ql[kc][3] = Ql[m0+g+8][kq+4];
    }

    float o[4][4];
    #pragma unroll
    for (int i = 0; i < 4; i++)
        #pragma unroll
        for (int j = 0; j < 4; j++) o[i][j] = 0.f;
    float m0r = -1e30f, m1r = -1e30f, l0r = 0.f, l1r = 0.f;

    // K/V loader mapping: 4 threads per key row (quarter-rows of 8 floats)
    const int vkey = t >> 2, vq = t & 3;

    for (int k0 = 0; k0 < CQ; k0 += 64) {
        __syncthreads();   // previous iteration's frag reads done

        // ---- load K quarter-row, split hi/lo ----
        {
            const int gk = k0 + vkey;
            float kf[8];
            if (gk < CQ) {
                const float* p = qkv + (basebq + gk) * 768 + CD + h * CDH + vq * 8;
                float4 a = *(const float4*)p;
                float4 c = *(const float4*)(p + 4);
                kf[0]=a.x; kf[1]=a.y; kf[2]=a.z; kf[3]=a.w;
                kf[4]=c.x; kf[5]=c.y; kf[6]=c.z; kf[7]=c.w;
            } else {
                #pragma unroll
                for (int j = 0; j < 8; j++) kf[j] = 0.f;
            }
            #pragma unroll
            for (int i = 0; i < 4; i++) {
                unsigned h0, l0;
                split2(kf[2*i], kf[2*i+1], h0, l0);
                Kh[vkey][vq*4 + i] = h0;
                Kl[vkey][vq*4 + i] = l0;
            }
        }

        // ---- load V quarter-row, transpose to [dim][keypair] via shfl(4) pairing ----
        {
            const int gk = k0 + vkey;
            float vf[8];
            if (gk < CQ) {
                const float* p = qkv + (basebq + gk) * 768 + 2*CD + h * CDH + vq * 8;
                float4 a = *(const float4*)p;
                float4 c = *(const float4*)(p + 4);
                vf[0]=a.x; vf[1]=a.y; vf[2]=a.z; vf[3]=a.w;
                vf[4]=c.x; vf[5]=c.y; vf[6]=c.z; vf[7]=c.w;
            } else {
                #pragma unroll
                for (int j = 0; j < 8; j++) vf[j] = 0.f;
            }
            const int kp = vkey >> 1;
            #pragma unroll
            for (int j = 0; j < 8; j++) {
                float other = __shfl_xor_sync(0xffffffffu, vf[j], 4);
                if ((t & 4) == 0) {
                    unsigned hh, ll;
                    split2(vf[j], other, hh, ll);
                    VTh[vq*8 + j][kp] = hh;
                    VTl[vq*8 + j][kp] = ll;
                }
            }
        }
        __syncthreads();

        // ---- scores S = Q K^T (bf16x3) ----
        float s[8][4];
        #pragma unroll
        for (int nt = 0; nt < 8; nt++)
            #pragma unroll
            for (int j = 0; j < 4; j++) s[nt][j] = 0.f;

        #pragma unroll
        for (int kc = 0; kc < 2; kc++) {
            const int kq = kc * 8 + tg;
            #pragma unroll
            for (int nt = 0; nt < 8; nt++) {
                const int nn = nt * 8 + g;
                const unsigned kh0 = Kh[nn][kq], kh1 = Kh[nn][kq+4];
                const unsigned kl0 = Kl[nn][kq], kl1 = Kl[nn][kq+4];
                mma_bf16(s[nt], ql[kc], kh0, kh1);
                mma_bf16(s[nt], qh[kc], kl0, kl1);
                mma_bf16(s[nt], qh[kc], kh0, kh1);
            }
        }

        // ---- key-tail masking ----
        if (k0 + 64 > CQ) {
            #pragma unroll
            for (int nt = 0; nt < 8; nt++) {
                const int kk = k0 + nt * 8 + 2 * tg;
                if (kk     >= CQ) { s[nt][0] = -1e30f; s[nt][2] = -1e30f; }
                if (kk + 1 >= CQ) { s[nt][1] = -1e30f; s[nt][3] = -1e30f; }
            }
        }

        // ---- online softmax (rows g and g+8) ----
        float cm0 = -1e30f, cm1 = -1e30f;
        #pragma unroll
        for (int nt = 0; nt < 8; nt++) {
            cm0 = fmaxf(cm0, fmaxf(s[nt][0], s[nt][1]));
            cm1 = fmaxf(cm1, fmaxf(s[nt][2], s[nt][3]));
        }
        cm0 = fmaxf(cm0, __shfl_xor_sync(0xffffffffu, cm0, 1));
        cm0 = fmaxf(cm0, __shfl_xor_sync(0xffffffffu, cm0, 2));
        cm1 = fmaxf(cm1, __shfl_xor_sync(0xffffffffu, cm1, 1));
        cm1 = fmaxf(cm1, __shfl_xor_sync(0xffffffffu, cm1, 2));

        const float nm0 = fmaxf(m0r, cm0), nm1 = fmaxf(m1r, cm1);
        const float f0 = __expf(m0r - nm0), f1 = __expf(m1r - nm1);
        m0r = nm0; m1r = nm1;
        #pragma unroll
        for (int nt = 0; nt < 4; nt++) {
            o[nt][0] *= f0; o[nt][1] *= f0;
            o[nt][2] *= f1; o[nt][3] *= f1;
        }

        float ps0 = 0.f, ps1 = 0.f;
        #pragma unroll
        for (int kc = 0; kc < 4; kc++) {
            unsigned ph[4], pl[4];
            #pragma unroll
            for (int e = 0; e < 2; e++) {
                const int nt = 2*kc + e;
                const float p0 = __expf(s[nt][0] - nm0);
                const float p1 = __expf(s[nt][1] - nm0);
                const float p2 = __expf(s[nt][2] - nm1);
                const float p3 = __expf(s[nt][3] - nm1);
                ps0 += p0 + p1; ps1 += p2 + p3;
                unsigned hh0, ll0, hh1, ll1;
                split2(p0, p1, hh0, ll0);
                split2(p2, p3, hh1, ll1);
                ph[2*e]   = hh0; pl[2*e]   = ll0;
                ph[2*e+1] = hh1; pl[2*e+1] = ll1;
            }
            const int kq = kc * 8 + tg;
            #pragma unroll
            for (int ntd = 0; ntd < 4; ntd++) {
                const int nn = ntd * 8 + g;
                const unsigned vh0 = VTh[nn][kq], vh1 = VTh[nn][kq+4];
                const unsigned vl0 = VTl[nn][kq], vl1 = VTl[nn][kq+4];
                mma_bf16(o[ntd], pl, vh0, vh1);
                mma_bf16(o[ntd], ph, vl0, vl1);
                mma_bf16(o[ntd], ph, vh0, vh1);
            }
        }
        ps0 += __shfl_xor_sync(0xffffffffu, ps0, 1);
        ps0 += __shfl_xor_sync(0xffffffffu, ps0, 2);
        ps1 += __shfl_xor_sync(0xffffffffu, ps1, 1);
        ps1 += __shfl_xor_sync(0xffffffffu, ps1, 2);
        l0r = l0r * f0 + ps0;
        l1r = l1r * f1 + ps1;
    }

    // ---- epilogue ----
    const float inv0 = 1.f / l0r, inv1 = 1.f / l1r;
    const int gq0 = q0 + m0 + g, gq1 = gq0 + 8;
    #pragma unroll
    for (int nt = 0; nt < 4; nt++) {
        const int d = h * CDH + nt * 8 + 2 * tg;
        if (gq0 < CQ)
            *(float2*)&out[(basebq + gq0) * CD + d] = make_float2(o[nt][0]*inv0, o[nt][1]*inv0);
        if (gq1 < CQ)
            *(float2*)&out[(basebq + gq1) * CD + d] = make_float2(o[nt][2]*inv1, o[nt][3]*inv1);
    }
}

// ------------------------- fused residual-add + LayerNorm (+ optional qpos-add) -------------------------
__global__ void add_ln_kernel(const float* __restrict__ a, const float* __restrict__ r,
                              const float* __restrict__ g, const float* __restrict__ be,
                              float* __restrict__ out, float* __restrict__ out2,
                              const float* __restrict__ qpos, float* __restrict__ xpq) {
    int row = blockIdx.x, t = threadIdx.x;   // 256 threads, D=256
    size_t idx = (size_t)row * CD + t;
    float v = a[idx] + r[idx];

    __shared__ float red[8];
    __shared__ float stat[2];

    float s = v;
    #pragma unroll
    for (int o = 16; o > 0; o >>= 1) s += __shfl_xor_sync(0xffffffffu, s, o);
    if ((t & 31) == 0) red[t >> 5] = s;
    __syncthreads();
    if (t == 0) {
        float tot = 0.f;
        #pragma unroll
        for (int i = 0; i < 8; i++) tot += red[i];
        stat[0] = tot * (1.f / CD);
    }
    __syncthreads();
    float mu = stat[0];
    float d = v - mu;
    float s2 = d * d;
    #pragma unroll
    for (int o = 16; o > 0; o >>= 1) s2 += __shfl_xor_sync(0xffffffffu, s2, o);
    if ((t & 31) == 0) red[t >> 5] = s2;
    __syncthreads();
    if (t == 0) {
        float tot = 0.f;
        #pragma unroll
        for (int i = 0; i < 8; i++) tot += red[i];
        stat[1] = tot * (1.f / CD);
    }
    __syncthreads();
    float o = d * rsqrtf(stat[1] + 1e-5f) * g[t] + be[t];
    out[idx] = o;
    if (out2) out2[idx] = o;
    if (qpos) xpq[idx] = o + qpos[idx];
}

// ------------------------- MSDA gather: one block per (b,q), warp = head -------------------------
__global__ void msda_kernel(const float* __restrict__ value, const float* __restrict__ offaw,
                            const float* __restrict__ refp,
                            const float* __restrict__ vr, float* __restrict__ out) {
    int bq = blockIdx.x;
    int b = bq / CQ;
    int t = threadIdx.x;          // 256 threads = 8 warps
    int h = t >> 5, lane = t & 31;

    float logit = (lane < 16) ? offaw[(size_t)bq * 384 + 256 + h * 16 + lane] : -1e30f;
    float m = logit;
    #pragma unroll
    for (int o = 8; o > 0; o >>= 1) m = fmaxf(m, __shfl_xor_sync(0xffffffffu, m, o, 16));
    float e = (lane < 16) ? __expf(logit - m) : 0.f;
    float es = e;
    #pragma unroll
    for (int o = 8; o > 0; o >>= 1) es += __shfl_xor_sync(0xffffffffu, es, o, 16);
    float p = e / es;

    float rx = refp[(size_t)bq * 2 + 0];
    float ry = refp[(size_t)bq * 2 + 1];

    const int   Ws[4] = {100, 50, 25, 13};
    const int   Hs[4] = {100, 50, 25, 13};
    const int   ST[4] = {0, 10000, 12500, 13125};

    const float* voff = value + (size_t)b * CS * CD + h * CDH + lane;
    float acc = 0.f;

    #pragma unroll
    for (int l = 0; l < 4; l++) {
        int W_ = Ws[l], H_ = Hs[l], st = ST[l];
        float vrx = vr[b * 8 + l * 2 + 0];
        float vry = vr[b * 8 + l * 2 + 1];
        float bx = rx * vrx * (float)W_ - 0.5f;
        float by = ry * vry * (float)H_ - 0.5f;
        #pragma unroll
        for (int pp = 0; pp < 4; pp++) {
            size_t oidx = (size_t)bq * 384 + (size_t)(((h * 4 + l) * 4 + pp) * 2);
            float x = bx + offaw[oidx + 0];
            float y = by + offaw[oidx + 1];
            float w = __shfl_sync(0xffffffffu, p, l * 4 + pp, 32);
            float x0f = floorf(x), y0f = floorf(y);
            float wx = x - x0f, wy = y - y0f;
            int x0 = (int)x0f, y0 = (int)y0f;

            float gsum = 0.f;
            {
                int xi = x0, yi = y0;
                if (xi >= 0 && xi < W_ && yi >= 0 && yi < H_)
                    gsum = fmaf(voff[(size_t)(st + yi * W_ + xi) * CD], (1.f - wx) * (1.f - wy), gsum);
            }
            {
                int xi = x0 + 1, yi = y0;
                if (xi >= 0 && xi < W_ && yi >= 0 && yi < H_)
                    gsum = fmaf(voff[(size_t)(st + yi * W_ + xi) * CD], wx * (1.f - wy), gsum);
            }
            {
                int xi = x0, yi = y0 + 1;
                if (xi >= 0 && xi < W_ && yi >= 0 && yi < H_)
                    gsum = fmaf(voff[(size_t)(st + yi * W_ + xi) * CD], (1.f - wx) * wy, gsum);
            }
            {
                int xi = x0 + 1, yi = y0 + 1;
                if (xi >= 0 && xi < W_ && yi >= 0 && yi < H_)
                    gsum = fmaf(voff[(size_t)(st + yi * W_ + xi) * CD], wx * wy, gsum);
            }
            acc = fmaf(w, gsum, acc);
        }
    }
    out[(size_t)bq * CD + h * CDH + lane] = acc;
}

// ------------------------- driver -------------------------
extern "C" void kernel_launch(void* const* d_in, const int* in_sizes, int n_in,
                              void* d_out, int out_size) {
    const float* tgt      = (const float*)d_in[0];
    const float* refp     = (const float*)d_in[1];
    const float* memory   = (const float*)d_in[2];
    const float* vratios  = (const float*)d_in[5];
    const float* qpos     = (const float*)d_in[6];
    const float* sa_in_w  = (const float*)d_in[7];
    const float* sa_in_b  = (const float*)d_in[8];
    const float* sa_out_w = (const float*)d_in[9];
    const float* sa_out_b = (const float*)d_in[10];
    const float* n1_g     = (const float*)d_in[11];
    const float* n1_b     = (const float*)d_in[12];
    const float* n2_g     = (const float*)d_in[13];
    const float* n2_b     = (const float*)d_in[14];
    const float* n3_g     = (const float*)d_in[15];
    const float* n3_b     = (const float*)d_in[16];
    const float* vp_w     = (const float*)d_in[17];
    const float* vp_b     = (const float*)d_in[18];
    const float* so_w     = (const float*)d_in[19];
    const float* so_b     = (const float*)d_in[20];
    const float* aw_w     = (const float*)d_in[21];
    const float* aw_b     = (const float*)d_in[22];
    const float* op_w     = (const float*)d_in[23];
    const float* op_b     = (const float*)d_in[24];
    const float* ff1_w    = (const float*)d_in[25];
    const float* ff1_b    = (const float*)d_in[26];
    const float* ff2_w    = (const float*)d_in[27];
    const float* ff2_b    = (const float*)d_in[28];

    float *value, *x, *xpq, *qkv, *attn, *t2, *offaw, *ms, *ffh, *sob;
    unsigned *wh, *wl;
    cudaGetSymbolAddress((void**)&value, g_value);
    cudaGetSymbolAddress((void**)&x,     g_x);
    cudaGetSymbolAddress((void**)&xpq,   g_xpq);
    cudaGetSymbolAddress((void**)&qkv,   g_qkv);
    cudaGetSymbolAddress((void**)&attn,  g_attn);
    cudaGetSymbolAddress((void**)&t2,    g_t2);
    cudaGetSymbolAddress((void**)&offaw, g_offaw);
    cudaGetSymbolAddress((void**)&ms,    g_ms);
    cudaGetSymbolAddress((void**)&ffh,   g_ffh);
    cudaGetSymbolAddress((void**)&sob,   g_sob);
    cudaGetSymbolAddress((void**)&wh,    g_wh);
    cudaGetSymbolAddress((void**)&wl,    g_wl);

    float* out = (float*)d_out;

    // single fused prologue kernel (splits, xpq, refs, sob) + state memcpy
    cudaMemcpyAsync(x, tgt, sizeof(float) * CBQ * CD, cudaMemcpyDeviceToDevice, 0);
    prologue_kernel<<<(PRO_TOTAL + 255)/256, 256>>>(
        vp_w, sa_in_w, sa_out_w, so_w, aw_w, op_w, ff1_w, ff2_w, wh, wl,
        tgt, qpos, xpq,
        refp, out + (size_t)CNLAYERS * CBQ * CD,
        so_b, aw_b, sob);

    // layer-invariant value projection (computed ONCE)
    gemm_bf3<false, 256><<<dim3(CD/128, (CBS + 127)/128), 256>>>(
        memory, wh + OFF_VP, wl + OFF_VP, vp_b, value, CBS, CD);

    const int MB  = (CBQ + 127) / 128;  // 57 row-blocks (128-row tiles)
    const int MB2 = (CBQ + 63) / 64;    // 113 row-blocks (64-row tiles)

    for (int L = 0; L < CNLAYERS; L++) {
        // ---- MHA ----
        gemm_bf3<false, 256><<<dim3(768/128, MB), 256>>>(
            xpq, wh + OFF_SAIN, wl + OFF_SAIN, sa_in_b, qkv, CBQ, 3*CD);
        flash_attn_tc<<<dim3((CQ + 127)/128, CNH, CB), 256>>>(qkv, attn);
        gemm_bf3_m64<256><<<dim3(CD/128, MB2), 256>>>(
            attn, wh + OFF_SAOU, wl + OFF_SAOU, sa_out_b, t2, CBQ, CD);
        add_ln_kernel<<<CBQ, CD>>>(xpq, t2, n1_g, n1_b, x, nullptr, nullptr, nullptr);

        // ---- MSDA ----
        gemm_bf3_m64<256><<<dim3(384/128, MB2), 256>>>(
            x, wh + OFF_SO, wl + OFF_SO, sob, offaw, CBQ, 384);
        msda_kernel<<<CBQ, 256>>>(value, offaw, refp, vratios, ms);
        gemm_bf3_m64<256><<<dim3(CD/128, MB2), 256>>>(
            ms, wh + OFF_OP, wl + OFF_OP, op_b, t2, CBQ, CD);
        add_ln_kernel<<<CBQ, CD>>>(x, t2, n2_g, n2_b, x, nullptr, nullptr, nullptr);

        // ---- FFN ----
        gemm_bf3<true, 256><<<dim3(CFF/128, MB), 256>>>(
            x, wh + OFF_FF1, wl + OFF_FF1, ff1_b, ffh, CBQ, CFF);
        gemm_bf3_m64<1024><<<dim3(CD/128, MB2), 256>>>(
            ffh, wh + OFF_FF2, wl + OFF_FF2, ff2_b, t2, CBQ, CD);
        // fused: x = LN(x + t2); out[L] = x; xpq = x + qpos (for next layer)
        add_ln_kernel<<<CBQ, CD>>>(x, t2, n3_g, n3_b, x, out + (size_t)L * CBQ * CD, qpos, xpq);
    }
}

// round 16
// speedup vs baseline: 1.0706x; 1.0706x over previous
#include <cuda_runtime.h>
#include <cuda_bf16.h>

// Problem constants
#define CB 8
#define CQ 900
#define CD 256
#define CNH 8
#define CDH 32
#define CFF 1024
#define CS 13294          // 100*100 + 50*50 + 25*25 + 13*13
#define CBQ (CB*CQ)       // 7200
#define CBS (CB*CS)       // 106352
#define CNLAYERS 6
#define ATTN_SCALE 0.17677669529663687f   // 1/sqrt(32)

// ------------------------- scratch (device globals) -------------------------
__device__ float g_value[CBS*CD];     // projected value, layer-invariant
__device__ float g_x    [CBQ*CD];     // decoder state
__device__ float g_xpq  [CBQ*CD];     // x + query_pos
__device__ float g_qkv  [CBQ*3*CD];
__device__ float g_attn [CBQ*CD];
__device__ float g_t2   [CBQ*CD];
__device__ float g_offaw[CBQ*384];    // fused sampling offsets (256) + aw logits (128)
__device__ float g_ms   [CBQ*CD];     // msda gather output
__device__ float g_ffh  [CBQ*CFF];    // ffn hidden
__device__ float g_sob  [384];        // concatenated so_b | aw_b

// split-weight planes (packed bf16 pairs along K). offsets in uint32 pairs.
#define OFF_VP   0
#define OFF_SAIN (OFF_VP   + 32768)    // vp:   256*256/2
#define OFF_SAOU (OFF_SAIN + 98304)    // sain: 768*256/2
#define OFF_SO   (OFF_SAOU + 32768)    // so+aw combined: 384*256/2
#define OFF_AW   (OFF_SO   + 32768)    // aw block lives right after so block
#define OFF_OP   (OFF_AW   + 16384)
#define OFF_FF1  (OFF_OP   + 32768)
#define OFF_FF2  (OFF_FF1  + 131072)
#define WSPLIT_TOTAL (OFF_FF2 + 131072) // 507904
__device__ unsigned g_wh[WSPLIT_TOTAL];
__device__ unsigned g_wl[WSPLIT_TOTAL];

// ------------------------- bf16 split helpers -------------------------
__device__ __forceinline__ void split2(float x, float y, unsigned& hi, unsigned& lo) {
    __nv_bfloat162 h = __floats2bfloat162_rn(x, y);
    hi = *reinterpret_cast<unsigned*>(&h);
    float rx = x - __bfloat162float(h.x);
    float ry = y - __bfloat162float(h.y);
    __nv_bfloat162 l = __floats2bfloat162_rn(rx, ry);
    lo = *reinterpret_cast<unsigned*>(&l);
}

__device__ __forceinline__ unsigned pack_bf2(float x, float y) {
    __nv_bfloat162 h = __floats2bfloat162_rn(x, y);
    return *reinterpret_cast<unsigned*>(&h);
}

__device__ __forceinline__ void mma_bf16(float* d, const unsigned* a, unsigned b0, unsigned b1) {
    asm volatile(
        "mma.sync.aligned.m16n8k16.row.col.f32.bf16.bf16.f32 "
        "{%0,%1,%2,%3}, {%4,%5,%6,%7}, {%8,%9}, {%0,%1,%2,%3};"
        : "+f"(d[0]), "+f"(d[1]), "+f"(d[2]), "+f"(d[3])
        : "r"(a[0]), "r"(a[1]), "r"(a[2]), "r"(a[3]), "r"(b0), "r"(b1));
}

// ------------------------- fused prologue: weight split + xpq add + refs + bias concat -------------------------
#define PRO_XPQ  (WSPLIT_TOTAL)                 // xpq = tgt + qpos : CBQ*CD elems
#define PRO_REFS (PRO_XPQ + CBQ*CD)             // write_refs      : CBQ*2 elems
#define PRO_SOB  (PRO_REFS + CB*CQ*2)           // sob concat      : 384 elems
#define PRO_TOTAL (PRO_SOB + 384)
__global__ void prologue_kernel(const float* __restrict__ vp,  const float* __restrict__ sain,
                                const float* __restrict__ saou,const float* __restrict__ so,
                                const float* __restrict__ aw,  const float* __restrict__ op,
                                const float* __restrict__ ff1, const float* __restrict__ ff2,
                                unsigned* __restrict__ wh, unsigned* __restrict__ wl,
                                const float* __restrict__ tgt, const float* __restrict__ qpos,
                                float* __restrict__ xpq,
                                const float* __restrict__ refp, float* __restrict__ outrefs,
                                const float* __restrict__ so_b, const float* __restrict__ aw_b,
                                float* __restrict__ sob) {
    int i = blockIdx.x * blockDim.x + threadIdx.x;
    if (i < WSPLIT_TOTAL) {
        const float* src; int off;
        if      (i < OFF_SAIN) { src = vp;   off = i - OFF_VP;   }
        else if (i < OFF_SAOU) { src = sain; off = i - OFF_SAIN; }
        else if (i < OFF_SO)   { src = saou; off = i - OFF_SAOU; }
        else if (i < OFF_AW)   { src = so;   off = i - OFF_SO;   }
        else if (i < OFF_OP)   { src = aw;   off = i - OFF_AW;   }
        else if (i < OFF_FF1)  { src = op;   off = i - OFF_OP;   }
        else if (i < OFF_FF2)  { src = ff1;  off = i - OFF_FF1;  }
        else                   { src = ff2;  off = i - OFF_FF2;  }
        unsigned h, l;
        split2(src[2*off], src[2*off+1], h, l);
        wh[i] = h; wl[i] = l;
    } else if (i < PRO_REFS) {
        int j = i - PRO_XPQ;
        xpq[j] = tgt[j] + qpos[j];
    } else if (i < PRO_SOB) {
        int j = i - PRO_REFS;
        float v = refp[j];
        const int n = CB * CQ * 2;
        #pragma unroll
        for (int L = 0; L < CNLAYERS; L++) outrefs[(size_t)L * n + j] = v;
    } else if (i < PRO_TOTAL) {
        int j = i - PRO_SOB;
        sob[j] = (j < 256) ? so_b[j] : aw_b[j - 256];
    }
}

// ------------------------- bf16x3 tensor-core GEMM (128x128 tile, K compile-time) -------------------------
template<bool RELU, int K>
__global__ __launch_bounds__(256)
void gemm_bf3(const float* __restrict__ A, const unsigned* __restrict__ Wh,
              const unsigned* __restrict__ Wl, const float* __restrict__ bias,
              float* __restrict__ C, int M, int N) {
    __shared__ unsigned Ah[128][20];
    __shared__ unsigned Al[128][20];
    __shared__ unsigned Bh[128][20];
    __shared__ unsigned Bl[128][20];

    const int tid  = threadIdx.x;
    const int lane = tid & 31, warp = tid >> 5;
    const int g = lane >> 2, tg = lane & 3;
    const int warpM = warp & 1, warpN = warp >> 1;   // 2 x 4 warps
    const int m0 = warpM * 64, n0 = warpN * 32;
    const int rowBase = blockIdx.y * 128, colBase = blockIdx.x * 128;
    constexpr int Kp = K >> 1;

    const int lrow  = tid >> 1;
    const int lhalf = tid & 1;
    const int kpb   = lhalf * 8;
    const int arow  = rowBase + lrow;
    const bool av   = arow < M;
    const float*    ap  = A  + (size_t)arow * K + lhalf * 16;
    const unsigned* bhp = Wh + (size_t)(colBase + lrow) * Kp + kpb;
    const unsigned* blp = Wl + (size_t)(colBase + lrow) * Kp + kpb;

    float acc[4][4][4];
    #pragma unroll
    for (int i = 0; i < 4; i++)
        #pragma unroll
        for (int j = 0; j < 4; j++)
            #pragma unroll
            for (int r = 0; r < 4; r++) acc[i][j][r] = 0.f;

    const float4 fz = make_float4(0.f, 0.f, 0.f, 0.f);
    float4 ra[4]; uint4 rbh[2], rbl[2];
    #pragma unroll
    for (int j = 0; j < 4; j++) ra[j] = av ? *(const float4*)(ap + 4*j) : fz;
    rbh[0] = *(const uint4*)(bhp);     rbh[1] = *(const uint4*)(bhp + 4);
    rbl[0] = *(const uint4*)(blp);     rbl[1] = *(const uint4*)(blp + 4);

    constexpr int ntiles = K >> 5;
    #pragma unroll
    for (int kt = 0; kt < ntiles; kt++) {
        #pragma unroll
        for (int j = 0; j < 4; j++) {
            unsigned h0, l0, h1, l1;
            split2(ra[j].x, ra[j].y, h0, l0);
            split2(ra[j].z, ra[j].w, h1, l1);
            Ah[lrow][kpb + 2*j]     = h0;  Ah[lrow][kpb + 2*j + 1] = h1;
            Al[lrow][kpb + 2*j]     = l0;  Al[lrow][kpb + 2*j + 1] = l1;
        }
        Bh[lrow][kpb+0] = rbh[0].x; Bh[lrow][kpb+1] = rbh[0].y;
        Bh[lrow][kpb+2] = rbh[0].z; Bh[lrow][kpb+3] = rbh[0].w;
        Bh[lrow][kpb+4] = rbh[1].x; Bh[lrow][kpb+5] = rbh[1].y;
        Bh[lrow][kpb+6] = rbh[1].z; Bh[lrow][kpb+7] = rbh[1].w;
        Bl[lrow][kpb+0] = rbl[0].x; Bl[lrow][kpb+1] = rbl[0].y;
        Bl[lrow][kpb+2] = rbl[0].z; Bl[lrow][kpb+3] = rbl[0].w;
        Bl[lrow][kpb+4] = rbl[1].x; Bl[lrow][kpb+5] = rbl[1].y;
        Bl[lrow][kpb+6] = rbl[1].z; Bl[lrow][kpb+7] = rbl[1].w;
        __syncthreads();

        if (kt + 1 < ntiles) {
            const int fo = (kt + 1) * 32;
            const int po = (kt + 1) * 16;
            #pragma unroll
            for (int j = 0; j < 4; j++) ra[j] = av ? *(const float4*)(ap + fo + 4*j) : fz;
            rbh[0] = *(const uint4*)(bhp + po); rbh[1] = *(const uint4*)(bhp + po + 4);
            rbl[0] = *(const uint4*)(blp + po); rbl[1] = *(const uint4*)(blp + po + 4);
        }

        #pragma unroll
        for (int ks = 0; ks < 2; ks++) {
            const int kq = ks * 8 + tg;
            unsigned af[4][4], alf[4][4];
            #pragma unroll
            for (int mt = 0; mt < 4; mt++) {
                const int mm = m0 + mt * 16 + g;
                af[mt][0]  = Ah[mm][kq];   af[mt][1]  = Ah[mm+8][kq];
                af[mt][2]  = Ah[mm][kq+4]; af[mt][3]  = Ah[mm+8][kq+4];
                alf[mt][0] = Al[mm][kq];   alf[mt][1] = Al[mm+8][kq];
                alf[mt][2] = Al[mm][kq+4]; alf[mt][3] = Al[mm+8][kq+4];
            }
            #pragma unroll
            for (int nt = 0; nt < 4; nt++) {
                const int nn = n0 + nt * 8 + g;
                const unsigned bh0 = Bh[nn][kq], bh1 = Bh[nn][kq+4];
                const unsigned bl0 = Bl[nn][kq], bl1 = Bl[nn][kq+4];
                #pragma unroll
                for (int mt = 0; mt < 4; mt++) mma_bf16(acc[mt][nt], alf[mt], bh0, bh1);
                #pragma unroll
                for (int mt = 0; mt < 4; mt++) mma_bf16(acc[mt][nt], af[mt],  bl0, bl1);
                #pragma unroll
                for (int mt = 0; mt < 4; mt++) mma_bf16(acc[mt][nt], af[mt],  bh0, bh1);
            }
        }
        __syncthreads();
    }

    #pragma unroll
    for (int mt = 0; mt < 4; mt++) {
        const int m  = rowBase + m0 + mt * 16 + g;
        #pragma unroll
        for (int nt = 0; nt < 4; nt++) {
            const int n = colBase + n0 + nt * 8 + 2 * tg;
            const float2 bv = *(const float2*)&bias[n];
            float* c = acc[mt][nt];
            if (m < M) {
                float2 o0 = make_float2(c[0] + bv.x, c[1] + bv.y);
                if (RELU) { o0.x = fmaxf(o0.x, 0.f); o0.y = fmaxf(o0.y, 0.f); }
                *(float2*)&C[(size_t)m * N + n] = o0;
            }
            if (m + 8 < M) {
                float2 o1 = make_float2(c[2] + bv.x, c[3] + bv.y);
                if (RELU) { o1.x = fmaxf(o1.x, 0.f); o1.y = fmaxf(o1.y, 0.f); }
                *(float2*)&C[(size_t)(m + 8) * N + n] = o1;
            }
        }
    }
}

// ------------------------- bf16x3 GEMM, 64x128 tile (for narrow-N outputs) -------------------------
template<int K>
__global__ __launch_bounds__(256)
void gemm_bf3_m64(const float* __restrict__ A, const unsigned* __restrict__ Wh,
                  const unsigned* __restrict__ Wl, const float* __restrict__ bias,
                  float* __restrict__ C, int M, int N) {
    __shared__ unsigned Ah[64][20];
    __shared__ unsigned Al[64][20];
    __shared__ unsigned Bh[128][20];
    __shared__ unsigned Bl[128][20];

    const int tid  = threadIdx.x;
    const int lane = tid & 31, warp = tid >> 5;
    const int g = lane >> 2, tg = lane & 3;
    const int warpM = warp & 1, warpN = warp >> 1;   // 2 x 4 warps
    const int m0 = warpM * 32, n0 = warpN * 32;
    const int rowBase = blockIdx.y * 64, colBase = blockIdx.x * 128;
    constexpr int Kp = K >> 1;

    const int arow = tid >> 2, aq = tid & 3;
    const int kpa  = aq * 4;
    const int garow = rowBase + arow;
    const bool av   = garow < M;
    const float* ap = A + (size_t)garow * K + aq * 8;

    const int lrow  = tid >> 1;
    const int lhalf = tid & 1;
    const int kpb   = lhalf * 8;
    const unsigned* bhp = Wh + (size_t)(colBase + lrow) * Kp + kpb;
    const unsigned* blp = Wl + (size_t)(colBase + lrow) * Kp + kpb;

    float acc[2][4][4];
    #pragma unroll
    for (int i = 0; i < 2; i++)
        #pragma unroll
        for (int j = 0; j < 4; j++)
            #pragma unroll
            for (int r = 0; r < 4; r++) acc[i][j][r] = 0.f;

    const float4 fz = make_float4(0.f, 0.f, 0.f, 0.f);
    float4 ra[2]; uint4 rbh[2], rbl[2];
    ra[0] = av ? *(const float4*)ap       : fz;
    ra[1] = av ? *(const float4*)(ap + 4) : fz;
    rbh[0] = *(const uint4*)(bhp);     rbh[1] = *(const uint4*)(bhp + 4);
    rbl[0] = *(const uint4*)(blp);     rbl[1] = *(const uint4*)(blp + 4);

    constexpr int ntiles = K >> 5;
    #pragma unroll
    for (int kt = 0; kt < ntiles; kt++) {
        {
            unsigned h0, l0, h1, l1;
            split2(ra[0].x, ra[0].y, h0, l0);
            split2(ra[0].z, ra[0].w, h1, l1);
            Ah[arow][kpa+0] = h0;  Ah[arow][kpa+1] = h1;
            Al[arow][kpa+0] = l0;  Al[arow][kpa+1] = l1;
            split2(ra[1].x, ra[1].y, h0, l0);
            split2(ra[1].z, ra[1].w, h1, l1);
            Ah[arow][kpa+2] = h0;  Ah[arow][kpa+3] = h1;
            Al[arow][kpa+2] = l0;  Al[arow][kpa+3] = l1;
        }
        Bh[lrow][kpb+0] = rbh[0].x; Bh[lrow][kpb+1] = rbh[0].y;
        Bh[lrow][kpb+2] = rbh[0].z; Bh[lrow][kpb+3] = rbh[0].w;
        Bh[lrow][kpb+4] = rbh[1].x; Bh[lrow][kpb+5] = rbh[1].y;
        Bh[lrow][kpb+6] = rbh[1].z; Bh[lrow][kpb+7] = rbh[1].w;
        Bl[lrow][kpb+0] = rbl[0].x; Bl[lrow][kpb+1] = rbl[0].y;
        Bl[lrow][kpb+2] = rbl[0].z; Bl[lrow][kpb+3] = rbl[0].w;
        Bl[lrow][kpb+4] = rbl[1].x; Bl[lrow][kpb+5] = rbl[1].y;
        Bl[lrow][kpb+6] = rbl[1].z; Bl[lrow][kpb+7] = rbl[1].w;
        __syncthreads();

        if (kt + 1 < ntiles) {
            const int fo = (kt + 1) * 32;
            const int po = (kt + 1) * 16;
            ra[0] = av ? *(const float4*)(ap + fo)     : fz;
            ra[1] = av ? *(const float4*)(ap + fo + 4) : fz;
            rbh[0] = *(const uint4*)(bhp + po); rbh[1] = *(const uint4*)(bhp + po + 4);
            rbl[0] = *(const uint4*)(blp + po); rbl[1] = *(const uint4*)(blp + po + 4);
        }

        #pragma unroll
        for (int ks = 0; ks < 2; ks++) {
            const int kq = ks * 8 + tg;
            unsigned af[2][4], alf[2][4];
            #pragma unroll
            for (int mt = 0; mt < 2; mt++) {
                const int mm = m0 + mt * 16 + g;
                af[mt][0]  = Ah[mm][kq];   af[mt][1]  = Ah[mm+8][kq];
                af[mt][2]  = Ah[mm][kq+4]; af[mt][3]  = Ah[mm+8][kq+4];
                alf[mt][0] = Al[mm][kq];   alf[mt][1] = Al[mm+8][kq];
                alf[mt][2] = Al[mm][kq+4]; alf[mt][3] = Al[mm+8][kq+4];
            }
            #pragma unroll
            for (int nt = 0; nt < 4; nt++) {
                const int nn = n0 + nt * 8 + g;
                const unsigned bh0 = Bh[nn][kq], bh1 = Bh[nn][kq+4];
                const unsigned bl0 = Bl[nn][kq], bl1 = Bl[nn][kq+4];
                #pragma unroll
                for (int mt = 0; mt < 2; mt++) mma_bf16(acc[mt][nt], alf[mt], bh0, bh1);
                #pragma unroll
                for (int mt = 0; mt < 2; mt++) mma_bf16(acc[mt][nt], af[mt],  bl0, bl1);
                #pragma unroll
                for (int mt = 0; mt < 2; mt++) mma_bf16(acc[mt][nt], af[mt],  bh0, bh1);
            }
        }
        __syncthreads();
    }

    #pragma unroll
    for (int mt = 0; mt < 2; mt++) {
        const int m  = rowBase + m0 + mt * 16 + g;
        #pragma unroll
        for (int nt = 0; nt < 4; nt++) {
            const int n = colBase + n0 + nt * 8 + 2 * tg;
            const float2 bv = *(const float2*)&bias[n];
            float* c = acc[mt][nt];
            if (m < M) {
                *(float2*)&C[(size_t)m * N + n] = make_float2(c[0] + bv.x, c[1] + bv.y);
            }
            if (m + 8 < M) {
                *(float2*)&C[(size_t)(m + 8) * N + n] = make_float2(c[2] + bv.x, c[3] + bv.y);
            }
        }
    }
}

// ------------------------- tensor-core flash attention (q-tile 128; single-bf16 P.V) -------------------------
// Block = (qtile 128, h, b), 256 threads; warp owns 16 q rows.
// QK^T stays bf16x3 (logit precision); P.V uses plain bf16 (softmax near-uniform => error ~1e-4).
__global__ __launch_bounds__(256)
void flash_attn_tc(const float* __restrict__ qkv, float* __restrict__ out) {
    const int qt = blockIdx.x, h = blockIdx.y, b = blockIdx.z;
    const int t = threadIdx.x, lane = t & 31, warp = t >> 5;
    const int g = lane >> 2, tg = lane & 3;

    __shared__ unsigned Qh[128][20], Ql[128][20];
    __shared__ unsigned Kh[64][20],  Kl[64][20];
    __shared__ unsigned VTh[32][36];

    const int q0 = qt * 128;
    const size_t basebq = (size_t)b * CQ;
    const int r = t >> 1, half = t & 1;          // Q loader: 2 threads/row over 128 rows

    // ---- load Q tile (pre-scaled), split hi/lo ----
    {
        const int gq = q0 + r;
        float4 v[4];
        if (gq < CQ) {
            const float* p = qkv + (basebq + gq) * 768 + h * CDH + half * 16;
            #pragma unroll
            for (int j = 0; j < 4; j++) v[j] = *(const float4*)(p + 4*j);
        } else {
            #pragma unroll
            for (int j = 0; j < 4; j++) v[j] = make_float4(0.f,0.f,0.f,0.f);
        }
        #pragma unroll
        for (int j = 0; j < 4; j++) {
            unsigned h0, l0, h1, l1;
            split2(v[j].x * ATTN_SCALE, v[j].y * ATTN_SCALE, h0, l0);
            split2(v[j].z * ATTN_SCALE, v[j].w * ATTN_SCALE, h1, l1);
            Qh[r][half*8 + 2*j]     = h0;  Qh[r][half*8 + 2*j + 1] = h1;
            Ql[r][half*8 + 2*j]     = l0;  Ql[r][half*8 + 2*j + 1] = l1;
        }
    }
    __syncthreads();

    // Q fragments (persist across k-tiles); warp owns rows m0..m0+15
    unsigned qh[2][4], ql[2][4];
    const int m0 = warp * 16;
    #pragma unroll
    for (int kc = 0; kc < 2; kc++) {
        const int kq = kc * 8 + tg;
        qh[kc][0] = Qh[m0+g][kq];   qh[kc][1] = Qh[m0+g+8][kq];
        qh[kc][2] = Qh[m0+g][kq+4]; qh[kc][3] = Qh[m0+g+8][kq+4];
        ql[kc][0] = Ql[m0+g][kq];   ql[kc][1] = Ql[m0+g+8][kq];
        ql[kc][2] = Ql[m0+g][kq+4]; ql[kc][3] = Ql[m0+g+8][kq+4];
    }

    float o[4][4];
    #pragma unroll
    for (int i = 0; i < 4; i++)
        #pragma unroll
        for (int j = 0; j < 4; j++) o[i][j] = 0.f;
    float m0r = -1e30f, m1r = -1e30f, l0r = 0.f, l1r = 0.f;

    // K/V loader mapping: 4 threads per key row (quarter-rows of 8 floats)
    const int vkey = t >> 2, vq = t & 3;

    for (int k0 = 0; k0 < CQ; k0 += 64) {
        __syncthreads();   // previous iteration's frag reads done

        // ---- load K quarter-row, split hi/lo ----
        {
            const int gk = k0 + vkey;
            float kf[8];
            if (gk < CQ) {
                const float* p = qkv + (basebq + gk) * 768 + CD + h * CDH + vq * 8;
                float4 a = *(const float4*)p;
                float4 c = *(const float4*)(p + 4);
                kf[0]=a.x; kf[1]=a.y; kf[2]=a.z; kf[3]=a.w;
                kf[4]=c.x; kf[5]=c.y; kf[6]=c.z; kf[7]=c.w;
            } else {
                #pragma unroll
                for (int j = 0; j < 8; j++) kf[j] = 0.f;
            }
            #pragma unroll
            for (int i = 0; i < 4; i++) {
                unsigned h0, l0;
                split2(kf[2*i], kf[2*i+1], h0, l0);
                Kh[vkey][vq*4 + i] = h0;
                Kl[vkey][vq*4 + i] = l0;
            }
        }

        // ---- load V quarter-row, transpose to [dim][keypair] via shfl(4) pairing (bf16 only) ----
        {
            const int gk = k0 + vkey;
            float vf[8];
            if (gk < CQ) {
                const float* p = qkv + (basebq + gk) * 768 + 2*CD + h * CDH + vq * 8;
                float4 a = *(const float4*)p;
                float4 c = *(const float4*)(p + 4);
                vf[0]=a.x; vf[1]=a.y; vf[2]=a.z; vf[3]=a.w;
                vf[4]=c.x; vf[5]=c.y; vf[6]=c.z; vf[7]=c.w;
            } else {
                #pragma unroll
                for (int j = 0; j < 8; j++) vf[j] = 0.f;
            }
            const int kp = vkey >> 1;
            #pragma unroll
            for (int j = 0; j < 8; j++) {
                float other = __shfl_xor_sync(0xffffffffu, vf[j], 4);
                if ((t & 4) == 0) {
                    VTh[vq*8 + j][kp] = pack_bf2(vf[j], other);
                }
            }
        }
        __syncthreads();

        // ---- scores S = Q K^T (bf16x3) ----
        float s[8][4];
        #pragma unroll
        for (int nt = 0; nt < 8; nt++)
            #pragma unroll
            for (int j = 0; j < 4; j++) s[nt][j] = 0.f;

        #pragma unroll
        for (int kc = 0; kc < 2; kc++) {
            const int kq = kc * 8 + tg;
            #pragma unroll
            for (int nt = 0; nt < 8; nt++) {
                const int nn = nt * 8 + g;
                const unsigned kh0 = Kh[nn][kq], kh1 = Kh[nn][kq+4];
                const unsigned kl0 = Kl[nn][kq], kl1 = Kl[nn][kq+4];
                mma_bf16(s[nt], ql[kc], kh0, kh1);
                mma_bf16(s[nt], qh[kc], kl0, kl1);
                mma_bf16(s[nt], qh[kc], kh0, kh1);
            }
        }

        // ---- key-tail masking ----
        if (k0 + 64 > CQ) {
            #pragma unroll
            for (int nt = 0; nt < 8; nt++) {
                const int kk = k0 + nt * 8 + 2 * tg;
                if (kk     >= CQ) { s[nt][0] = -1e30f; s[nt][2] = -1e30f; }
                if (kk + 1 >= CQ) { s[nt][1] = -1e30f; s[nt][3] = -1e30f; }
            }
        }

        // ---- online softmax (rows g and g+8) ----
        float cm0 = -1e30f, cm1 = -1e30f;
        #pragma unroll
        for (int nt = 0; nt < 8; nt++) {
            cm0 = fmaxf(cm0, fmaxf(s[nt][0], s[nt][1]));
            cm1 = fmaxf(cm1, fmaxf(s[nt][2], s[nt][3]));
        }
        cm0 = fmaxf(cm0, __shfl_xor_sync(0xffffffffu, cm0, 1));
        cm0 = fmaxf(cm0, __shfl_xor_sync(0xffffffffu, cm0, 2));
        cm1 = fmaxf(cm1, __shfl_xor_sync(0xffffffffu, cm1, 1));
        cm1 = fmaxf(cm1, __shfl_xor_sync(0xffffffffu, cm1, 2));

        const float nm0 = fmaxf(m0r, cm0), nm1 = fmaxf(m1r, cm1);
        const float f0 = __expf(m0r - nm0), f1 = __expf(m1r - nm1);
        m0r = nm0; m1r = nm1;
        #pragma unroll
        for (int nt = 0; nt < 4; nt++) {
            o[nt][0] *= f0; o[nt][1] *= f0;
            o[nt][2] *= f1; o[nt][3] *= f1;
        }

        float ps0 = 0.f, ps1 = 0.f;
        #pragma unroll
        for (int kc = 0; kc < 4; kc++) {
            unsigned ph[4];
            #pragma unroll
            for (int e = 0; e < 2; e++) {
                const int nt = 2*kc + e;
                const float p0 = __expf(s[nt][0] - nm0);
                const float p1 = __expf(s[nt][1] - nm0);
                const float p2 = __expf(s[nt][2] - nm1);
                const float p3 = __expf(s[nt][3] - nm1);
                ps0 += p0 + p1; ps1 += p2 + p3;
                ph[2*e]   = pack_bf2(p0, p1);
                ph[2*e+1] = pack_bf2(p2, p3);
            }
            const int kq = kc * 8 + tg;
            #pragma unroll
            for (int ntd = 0; ntd < 4; ntd++) {
                const int nn = ntd * 8 + g;
                const unsigned vh0 = VTh[nn][kq], vh1 = VTh[nn][kq+4];
                mma_bf16(o[ntd], ph, vh0, vh1);
            }
        }
        ps0 += __shfl_xor_sync(0xffffffffu, ps0, 1);
        ps0 += __shfl_xor_sync(0xffffffffu, ps0, 2);
        ps1 += __shfl_xor_sync(0xffffffffu, ps1, 1);
        ps1 += __shfl_xor_sync(0xffffffffu, ps1, 2);
        l0r = l0r * f0 + ps0;
        l1r = l1r * f1 + ps1;
    }

    // ---- epilogue ----
    const float inv0 = 1.f / l0r, inv1 = 1.f / l1r;
    const int gq0 = q0 + m0 + g, gq1 = gq0 + 8;
    #pragma unroll
    for (int nt = 0; nt < 4; nt++) {
        const int d = h * CDH + nt * 8 + 2 * tg;
        if (gq0 < CQ)
            *(float2*)&out[(basebq + gq0) * CD + d] = make_float2(o[nt][0]*inv0, o[nt][1]*inv0);
        if (gq1 < CQ)
            *(float2*)&out[(basebq + gq1) * CD + d] = make_float2(o[nt][2]*inv1, o[nt][3]*inv1);
    }
}

// ------------------------- fused residual-add + LayerNorm (+ optional qpos-add) -------------------------
__global__ void add_ln_kernel(const float* __restrict__ a, const float* __restrict__ r,
                              const float* __restrict__ g, const float* __restrict__ be,
                              float* __restrict__ out, float* __restrict__ out2,
                              const float* __restrict__ qpos, float* __restrict__ xpq) {
    int row = blockIdx.x, t = threadIdx.x;   // 256 threads, D=256
    size_t idx = (size_t)row * CD + t;
    float v = a[idx] + r[idx];

    __shared__ float red[8];
    __shared__ float stat[2];

    float s = v;
    #pragma unroll
    for (int o = 16; o > 0; o >>= 1) s += __shfl_xor_sync(0xffffffffu, s, o);
    if ((t & 31) == 0) red[t >> 5] = s;
    __syncthreads();
    if (t == 0) {
        float tot = 0.f;
        #pragma unroll
        for (int i = 0; i < 8; i++) tot += red[i];
        stat[0] = tot * (1.f / CD);
    }
    __syncthreads();
    float mu = stat[0];
    float d = v - mu;
    float s2 = d * d;
    #pragma unroll
    for (int o = 16; o > 0; o >>= 1) s2 += __shfl_xor_sync(0xffffffffu, s2, o);
    if ((t & 31) == 0) red[t >> 5] = s2;
    __syncthreads();
    if (t == 0) {
        float tot = 0.f;
        #pragma unroll
        for (int i = 0; i < 8; i++) tot += red[i];
        stat[1] = tot * (1.f / CD);
    }
    __syncthreads();
    float o = d * rsqrtf(stat[1] + 1e-5f) * g[t] + be[t];
    out[idx] = o;
    if (out2) out2[idx] = o;
    if (qpos) xpq[idx] = o + qpos[idx];
}

// ------------------------- MSDA gather: one block per (b,q), warp = head -------------------------
__global__ void msda_kernel(const float* __restrict__ value, const float* __restrict__ offaw,
                            const float* __restrict__ refp,
                            const float* __restrict__ vr, float* __restrict__ out) {
    int bq = blockIdx.x;
    int b = bq / CQ;
    int t = threadIdx.x;          // 256 threads = 8 warps
    int h = t >> 5, lane = t & 31;

    float logit = (lane < 16) ? offaw[(size_t)bq * 384 + 256 + h * 16 + lane] : -1e30f;
    float m = logit;
    #pragma unroll
    for (int o = 8; o > 0; o >>= 1) m = fmaxf(m, __shfl_xor_sync(0xffffffffu, m, o, 16));
    float e = (lane < 16) ? __expf(logit - m) : 0.f;
    float es = e;
    #pragma unroll
    for (int o = 8; o > 0; o >>= 1) es += __shfl_xor_sync(0xffffffffu, es, o, 16);
    float p = e / es;

    float rx = refp[(size_t)bq * 2 + 0];
    float ry = refp[(size_t)bq * 2 + 1];

    const int   Ws[4] = {100, 50, 25, 13};
    const int   Hs[4] = {100, 50, 25, 13};
    const int   ST[4] = {0, 10000, 12500, 13125};

    const float* voff = value + (size_t)b * CS * CD + h * CDH + lane;
    float acc = 0.f;

    #pragma unroll
    for (int l = 0; l < 4; l++) {
        int W_ = Ws[l], H_ = Hs[l], st = ST[l];
        float vrx = vr[b * 8 + l * 2 + 0];
        float vry = vr[b * 8 + l * 2 + 1];
        float bx = rx * vrx * (float)W_ - 0.5f;
        float by = ry * vry * (float)H_ - 0.5f;
        #pragma unroll
        for (int pp = 0; pp < 4; pp++) {
            size_t oidx = (size_t)bq * 384 + (size_t)(((h * 4 + l) * 4 + pp) * 2);
            float x = bx + offaw[oidx + 0];
            float y = by + offaw[oidx + 1];
            float w = __shfl_sync(0xffffffffu, p, l * 4 + pp, 32);
            float x0f = floorf(x), y0f = floorf(y);
            float wx = x - x0f, wy = y - y0f;
            int x0 = (int)x0f, y0 = (int)y0f;

            float gsum = 0.f;
            {
                int xi = x0, yi = y0;
                if (xi >= 0 && xi < W_ && yi >= 0 && yi < H_)
                    gsum = fmaf(voff[(size_t)(st + yi * W_ + xi) * CD], (1.f - wx) * (1.f - wy), gsum);
            }
            {
                int xi = x0 + 1, yi = y0;
                if (xi >= 0 && xi < W_ && yi >= 0 && yi < H_)
                    gsum = fmaf(voff[(size_t)(st + yi * W_ + xi) * CD], wx * (1.f - wy), gsum);
            }
            {
                int xi = x0, yi = y0 + 1;
                if (xi >= 0 && xi < W_ && yi >= 0 && yi < H_)
                    gsum = fmaf(voff[(size_t)(st + yi * W_ + xi) * CD], (1.f - wx) * wy, gsum);
            }
            {
                int xi = x0 + 1, yi = y0 + 1;
                if (xi >= 0 && xi < W_ && yi >= 0 && yi < H_)
                    gsum = fmaf(voff[(size_t)(st + yi * W_ + xi) * CD], wx * wy, gsum);
            }
            acc = fmaf(w, gsum, acc);
        }
    }
    out[(size_t)bq * CD + h * CDH + lane] = acc;
}

// ------------------------- driver -------------------------
extern "C" void kernel_launch(void* const* d_in, const int* in_sizes, int n_in,
                              void* d_out, int out_size) {
    const float* tgt      = (const float*)d_in[0];
    const float* refp     = (const float*)d_in[1];
    const float* memory   = (const float*)d_in[2];
    const float* vratios  = (const float*)d_in[5];
    const float* qpos     = (const float*)d_in[6];
    const float* sa_in_w  = (const float*)d_in[7];
    const float* sa_in_b  = (const float*)d_in[8];
    const float* sa_out_w = (const float*)d_in[9];
    const float* sa_out_b = (const float*)d_in[10];
    const float* n1_g     = (const float*)d_in[11];
    const float* n1_b     = (const float*)d_in[12];
    const float* n2_g     = (const float*)d_in[13];
    const float* n2_b     = (const float*)d_in[14];
    const float* n3_g     = (const float*)d_in[15];
    const float* n3_b     = (const float*)d_in[16];
    const float* vp_w     = (const float*)d_in[17];
    const float* vp_b     = (const float*)d_in[18];
    const float* so_w     = (const float*)d_in[19];
    const float* so_b     = (const float*)d_in[20];
    const float* aw_w     = (const float*)d_in[21];
    const float* aw_b     = (const float*)d_in[22];
    const float* op_w     = (const float*)d_in[23];
    const float* op_b     = (const float*)d_in[24];
    const float* ff1_w    = (const float*)d_in[25];
    const float* ff1_b    = (const float*)d_in[26];
    const float* ff2_w    = (const float*)d_in[27];
    const float* ff2_b    = (const float*)d_in[28];

    float *value, *x, *xpq, *qkv, *attn, *t2, *offaw, *ms, *ffh, *sob;
    unsigned *wh, *wl;
    cudaGetSymbolAddress((void**)&value, g_value);
    cudaGetSymbolAddress((void**)&x,     g_x);
    cudaGetSymbolAddress((void**)&xpq,   g_xpq);
    cudaGetSymbolAddress((void**)&qkv,   g_qkv);
    cudaGetSymbolAddress((void**)&attn,  g_attn);
    cudaGetSymbolAddress((void**)&t2,    g_t2);
    cudaGetSymbolAddress((void**)&offaw, g_offaw);
    cudaGetSymbolAddress((void**)&ms,    g_ms);
    cudaGetSymbolAddress((void**)&ffh,   g_ffh);
    cudaGetSymbolAddress((void**)&sob,   g_sob);
    cudaGetSymbolAddress((void**)&wh,    g_wh);
    cudaGetSymbolAddress((void**)&wl,    g_wl);

    float* out = (float*)d_out;

    // single fused prologue kernel (splits, xpq, refs, sob) + state memcpy
    cudaMemcpyAsync(x, tgt, sizeof(float) * CBQ * CD, cudaMemcpyDeviceToDevice, 0);
    prologue_kernel<<<(PRO_TOTAL + 255)/256, 256>>>(
        vp_w, sa_in_w, sa_out_w, so_w, aw_w, op_w, ff1_w, ff2_w, wh, wl,
        tgt, qpos, xpq,
        refp, out + (size_t)CNLAYERS * CBQ * CD,
        so_b, aw_b, sob);

    // layer-invariant value projection (computed ONCE)
    gemm_bf3<false, 256><<<dim3(CD/128, (CBS + 127)/128), 256>>>(
        memory, wh + OFF_VP, wl + OFF_VP, vp_b, value, CBS, CD);

    const int MB  = (CBQ + 127) / 128;  // 57 row-blocks (128-row tiles)
    const int MB2 = (CBQ + 63) / 64;    // 113 row-blocks (64-row tiles)

    for (int L = 0; L < CNLAYERS; L++) {
        // ---- MHA ----
        gemm_bf3<false, 256><<<dim3(768/128, MB), 256>>>(
            xpq, wh + OFF_SAIN, wl + OFF_SAIN, sa_in_b, qkv, CBQ, 3*CD);
        flash_attn_tc<<<dim3((CQ + 127)/128, CNH, CB), 256>>>(qkv, attn);
        gemm_bf3_m64<256><<<dim3(CD/128, MB2), 256>>>(
            attn, wh + OFF_SAOU, wl + OFF_SAOU, sa_out_b, t2, CBQ, CD);
        add_ln_kernel<<<CBQ, CD>>>(xpq, t2, n1_g, n1_b, x, nullptr, nullptr, nullptr);

        // ---- MSDA ----
        gemm_bf3_m64<256><<<dim3(384/128, MB2), 256>>>(
            x, wh + OFF_SO, wl + OFF_SO, sob, offaw, CBQ, 384);
        msda_kernel<<<CBQ, 256>>>(value, offaw, refp, vratios, ms);
        gemm_bf3_m64<256><<<dim3(CD/128, MB2), 256>>>(
            ms, wh + OFF_OP, wl + OFF_OP, op_b, t2, CBQ, CD);
        add_ln_kernel<<<CBQ, CD>>>(x, t2, n2_g, n2_b, x, nullptr, nullptr, nullptr);

        // ---- FFN ----
        gemm_bf3<true, 256><<<dim3(CFF/128, MB), 256>>>(
            x, wh + OFF_FF1, wl + OFF_FF1, ff1_b, ffh, CBQ, CFF);
        gemm_bf3_m64<1024><<<dim3(CD/128, MB2), 256>>>(
            ffh, wh + OFF_FF2, wl + OFF_FF2, ff2_b, t2, CBQ, CD);
        // fused: x = LN(x + t2); out[L] = x; xpq = x + qpos (for next layer)
        add_ln_kernel<<<CBQ, CD>>>(x, t2, n3_g, n3_b, x, out + (size_t)L * CBQ * CD, qpos, xpq);
    }
}

// round 17
// speedup vs baseline: 1.1152x; 1.0416x over previous
#include <cuda_runtime.h>
#include <cuda_bf16.h>

// Problem constants
#define CB 8
#define CQ 900
#define CD 256
#define CNH 8
#define CDH 32
#define CFF 1024
#define CS 13294          // 100*100 + 50*50 + 25*25 + 13*13
#define CBQ (CB*CQ)       // 7200
#define CBS (CB*CS)       // 106352
#define CNLAYERS 6
#define ATTN_SCALE 0.17677669529663687f   // 1/sqrt(32)

// ------------------------- scratch (device globals) -------------------------
__device__ float g_value[CBS*CD];     // projected value, layer-invariant
__device__ float g_x    [CBQ*CD];     // decoder state
__device__ float g_xpq  [CBQ*CD];     // x + query_pos
__device__ float g_qkv  [CBQ*3*CD];
__device__ float g_attn [CBQ*CD];
__device__ float g_t2   [CBQ*CD];
__device__ float g_offaw[CBQ*384];    // fused sampling offsets (256) + aw logits (128)
__device__ float g_ms   [CBQ*CD];     // msda gather output
__device__ float g_ffh  [CBQ*CFF];    // ffn hidden
__device__ float g_sob  [384];        // concatenated so_b | aw_b

// split-weight planes (packed bf16 pairs along K). offsets in uint32 pairs.
#define OFF_VP   0
#define OFF_SAIN (OFF_VP   + 32768)    // vp:   256*256/2
#define OFF_SAOU (OFF_SAIN + 98304)    // sain: 768*256/2
#define OFF_SO   (OFF_SAOU + 32768)    // so+aw combined: 384*256/2
#define OFF_AW   (OFF_SO   + 32768)    // aw block lives right after so block
#define OFF_OP   (OFF_AW   + 16384)
#define OFF_FF1  (OFF_OP   + 32768)
#define OFF_FF2  (OFF_FF1  + 131072)
#define WSPLIT_TOTAL (OFF_FF2 + 131072) // 507904
__device__ unsigned g_wh[WSPLIT_TOTAL];
__device__ unsigned g_wl[WSPLIT_TOTAL];

// ------------------------- bf16 split helpers -------------------------
__device__ __forceinline__ void split2(float x, float y, unsigned& hi, unsigned& lo) {
    __nv_bfloat162 h = __floats2bfloat162_rn(x, y);
    hi = *reinterpret_cast<unsigned*>(&h);
    float rx = x - __bfloat162float(h.x);
    float ry = y - __bfloat162float(h.y);
    __nv_bfloat162 l = __floats2bfloat162_rn(rx, ry);
    lo = *reinterpret_cast<unsigned*>(&l);
}

__device__ __forceinline__ unsigned pack_bf2(float x, float y) {
    __nv_bfloat162 h = __floats2bfloat162_rn(x, y);
    return *reinterpret_cast<unsigned*>(&h);
}

__device__ __forceinline__ void mma_bf16(float* d, const unsigned* a, unsigned b0, unsigned b1) {
    asm volatile(
        "mma.sync.aligned.m16n8k16.row.col.f32.bf16.bf16.f32 "
        "{%0,%1,%2,%3}, {%4,%5,%6,%7}, {%8,%9}, {%0,%1,%2,%3};"
        : "+f"(d[0]), "+f"(d[1]), "+f"(d[2]), "+f"(d[3])
        : "r"(a[0]), "r"(a[1]), "r"(a[2]), "r"(a[3]), "r"(b0), "r"(b1));
}

// ------------------------- fused prologue: weight split + xpq add + refs + bias concat -------------------------
#define PRO_XPQ  (WSPLIT_TOTAL)                 // xpq = tgt + qpos : CBQ*CD elems
#define PRO_REFS (PRO_XPQ + CBQ*CD)             // write_refs      : CBQ*2 elems
#define PRO_SOB  (PRO_REFS + CB*CQ*2)           // sob concat      : 384 elems
#define PRO_TOTAL (PRO_SOB + 384)
__global__ void prologue_kernel(const float* __restrict__ vp,  const float* __restrict__ sain,
                                const float* __restrict__ saou,const float* __restrict__ so,
                                const float* __restrict__ aw,  const float* __restrict__ op,
                                const float* __restrict__ ff1, const float* __restrict__ ff2,
                                unsigned* __restrict__ wh, unsigned* __restrict__ wl,
                                const float* __restrict__ tgt, const float* __restrict__ qpos,
                                float* __restrict__ xpq,
                                const float* __restrict__ refp, float* __restrict__ outrefs,
                                const float* __restrict__ so_b, const float* __restrict__ aw_b,
                                float* __restrict__ sob) {
    int i = blockIdx.x * blockDim.x + threadIdx.x;
    if (i < WSPLIT_TOTAL) {
        const float* src; int off;
        if      (i < OFF_SAIN) { src = vp;   off = i - OFF_VP;   }
        else if (i < OFF_SAOU) { src = sain; off = i - OFF_SAIN; }
        else if (i < OFF_SO)   { src = saou; off = i - OFF_SAOU; }
        else if (i < OFF_AW)   { src = so;   off = i - OFF_SO;   }
        else if (i < OFF_OP)   { src = aw;   off = i - OFF_AW;   }
        else if (i < OFF_FF1)  { src = op;   off = i - OFF_OP;   }
        else if (i < OFF_FF2)  { src = ff1;  off = i - OFF_FF1;  }
        else                   { src = ff2;  off = i - OFF_FF2;  }
        unsigned h, l;
        split2(src[2*off], src[2*off+1], h, l);
        wh[i] = h; wl[i] = l;
    } else if (i < PRO_REFS) {
        int j = i - PRO_XPQ;
        xpq[j] = tgt[j] + qpos[j];
    } else if (i < PRO_SOB) {
        int j = i - PRO_REFS;
        float v = refp[j];
        const int n = CB * CQ * 2;
        #pragma unroll
        for (int L = 0; L < CNLAYERS; L++) outrefs[(size_t)L * n + j] = v;
    } else if (i < PRO_TOTAL) {
        int j = i - PRO_SOB;
        sob[j] = (j < 256) ? so_b[j] : aw_b[j - 256];
    }
}

// ------------------------- bf16x3 tensor-core GEMM (128x128 tile, K compile-time) -------------------------
template<bool RELU, int K>
__global__ __launch_bounds__(256)
void gemm_bf3(const float* __restrict__ A, const unsigned* __restrict__ Wh,
              const unsigned* __restrict__ Wl, const float* __restrict__ bias,
              float* __restrict__ C, int M, int N) {
    __shared__ unsigned Ah[128][20];
    __shared__ unsigned Al[128][20];
    __shared__ unsigned Bh[128][20];
    __shared__ unsigned Bl[128][20];

    const int tid  = threadIdx.x;
    const int lane = tid & 31, warp = tid >> 5;
    const int g = lane >> 2, tg = lane & 3;
    const int warpM = warp & 1, warpN = warp >> 1;   // 2 x 4 warps
    const int m0 = warpM * 64, n0 = warpN * 32;
    const int rowBase = blockIdx.y * 128, colBase = blockIdx.x * 128;
    constexpr int Kp = K >> 1;

    const int lrow  = tid >> 1;
    const int lhalf = tid & 1;
    const int kpb   = lhalf * 8;
    const int arow  = rowBase + lrow;
    const bool av   = arow < M;
    const float*    ap  = A  + (size_t)arow * K + lhalf * 16;
    const unsigned* bhp = Wh + (size_t)(colBase + lrow) * Kp + kpb;
    const unsigned* blp = Wl + (size_t)(colBase + lrow) * Kp + kpb;

    float acc[4][4][4];
    #pragma unroll
    for (int i = 0; i < 4; i++)
        #pragma unroll
        for (int j = 0; j < 4; j++)
            #pragma unroll
            for (int r = 0; r < 4; r++) acc[i][j][r] = 0.f;

    const float4 fz = make_float4(0.f, 0.f, 0.f, 0.f);
    float4 ra[4]; uint4 rbh[2], rbl[2];
    #pragma unroll
    for (int j = 0; j < 4; j++) ra[j] = av ? *(const float4*)(ap + 4*j) : fz;
    rbh[0] = *(const uint4*)(bhp);     rbh[1] = *(const uint4*)(bhp + 4);
    rbl[0] = *(const uint4*)(blp);     rbl[1] = *(const uint4*)(blp + 4);

    constexpr int ntiles = K >> 5;
    #pragma unroll
    for (int kt = 0; kt < ntiles; kt++) {
        #pragma unroll
        for (int j = 0; j < 4; j++) {
            unsigned h0, l0, h1, l1;
            split2(ra[j].x, ra[j].y, h0, l0);
            split2(ra[j].z, ra[j].w, h1, l1);
            Ah[lrow][kpb + 2*j]     = h0;  Ah[lrow][kpb + 2*j + 1] = h1;
            Al[lrow][kpb + 2*j]     = l0;  Al[lrow][kpb + 2*j + 1] = l1;
        }
        Bh[lrow][kpb+0] = rbh[0].x; Bh[lrow][kpb+1] = rbh[0].y;
        Bh[lrow][kpb+2] = rbh[0].z; Bh[lrow][kpb+3] = rbh[0].w;
        Bh[lrow][kpb+4] = rbh[1].x; Bh[lrow][kpb+5] = rbh[1].y;
        Bh[lrow][kpb+6] = rbh[1].z; Bh[lrow][kpb+7] = rbh[1].w;
        Bl[lrow][kpb+0] = rbl[0].x; Bl[lrow][kpb+1] = rbl[0].y;
        Bl[lrow][kpb+2] = rbl[0].z; Bl[lrow][kpb+3] = rbl[0].w;
        Bl[lrow][kpb+4] = rbl[1].x; Bl[lrow][kpb+5] = rbl[1].y;
        Bl[lrow][kpb+6] = rbl[1].z; Bl[lrow][kpb+7] = rbl[1].w;
        __syncthreads();

        if (kt + 1 < ntiles) {
            const int fo = (kt + 1) * 32;
            const int po = (kt + 1) * 16;
            #pragma unroll
            for (int j = 0; j < 4; j++) ra[j] = av ? *(const float4*)(ap + fo + 4*j) : fz;
            rbh[0] = *(const uint4*)(bhp + po); rbh[1] = *(const uint4*)(bhp + po + 4);
            rbl[0] = *(const uint4*)(blp + po); rbl[1] = *(const uint4*)(blp + po + 4);
        }

        #pragma unroll
        for (int ks = 0; ks < 2; ks++) {
            const int kq = ks * 8 + tg;
            unsigned af[4][4], alf[4][4];
            #pragma unroll
            for (int mt = 0; mt < 4; mt++) {
                const int mm = m0 + mt * 16 + g;
                af[mt][0]  = Ah[mm][kq];   af[mt][1]  = Ah[mm+8][kq];
                af[mt][2]  = Ah[mm][kq+4]; af[mt][3]  = Ah[mm+8][kq+4];
                alf[mt][0] = Al[mm][kq];   alf[mt][1] = Al[mm+8][kq];
                alf[mt][2] = Al[mm][kq+4]; alf[mt][3] = Al[mm+8][kq+4];
            }
            #pragma unroll
            for (int nt = 0; nt < 4; nt++) {
                const int nn = n0 + nt * 8 + g;
                const unsigned bh0 = Bh[nn][kq], bh1 = Bh[nn][kq+4];
                const unsigned bl0 = Bl[nn][kq], bl1 = Bl[nn][kq+4];
                #pragma unroll
                for (int mt = 0; mt < 4; mt++) mma_bf16(acc[mt][nt], alf[mt], bh0, bh1);
                #pragma unroll
                for (int mt = 0; mt < 4; mt++) mma_bf16(acc[mt][nt], af[mt],  bl0, bl1);
                #pragma unroll
                for (int mt = 0; mt < 4; mt++) mma_bf16(acc[mt][nt], af[mt],  bh0, bh1);
            }
        }
        __syncthreads();
    }

    #pragma unroll
    for (int mt = 0; mt < 4; mt++) {
        const int m  = rowBase + m0 + mt * 16 + g;
        #pragma unroll
        for (int nt = 0; nt < 4; nt++) {
            const int n = colBase + n0 + nt * 8 + 2 * tg;
            const float2 bv = *(const float2*)&bias[n];
            float* c = acc[mt][nt];
            if (m < M) {
                float2 o0 = make_float2(c[0] + bv.x, c[1] + bv.y);
                if (RELU) { o0.x = fmaxf(o0.x, 0.f); o0.y = fmaxf(o0.y, 0.f); }
                *(float2*)&C[(size_t)m * N + n] = o0;
            }
            if (m + 8 < M) {
                float2 o1 = make_float2(c[2] + bv.x, c[3] + bv.y);
                if (RELU) { o1.x = fmaxf(o1.x, 0.f); o1.y = fmaxf(o1.y, 0.f); }
                *(float2*)&C[(size_t)(m + 8) * N + n] = o1;
            }
        }
    }
}

// ------------------------- bf16x3 GEMM, 64x128 tile (for narrow-N outputs) -------------------------
template<int K>
__global__ __launch_bounds__(256)
void gemm_bf3_m64(const float* __restrict__ A, const unsigned* __restrict__ Wh,
                  const unsigned* __restrict__ Wl, const float* __restrict__ bias,
                  float* __restrict__ C, int M, int N) {
    __shared__ unsigned Ah[64][20];
    __shared__ unsigned Al[64][20];
    __shared__ unsigned Bh[128][20];
    __shared__ unsigned Bl[128][20];

    const int tid  = threadIdx.x;
    const int lane = tid & 31, warp = tid >> 5;
    const int g = lane >> 2, tg = lane & 3;
    const int warpM = warp & 1, warpN = warp >> 1;   // 2 x 4 warps
    const int m0 = warpM * 32, n0 = warpN * 32;
    const int rowBase = blockIdx.y * 64, colBase = blockIdx.x * 128;
    constexpr int Kp = K >> 1;

    const int arow = tid >> 2, aq = tid & 3;
    const int kpa  = aq * 4;
    const int garow = rowBase + arow;
    const bool av   = garow < M;
    const float* ap = A + (size_t)garow * K + aq * 8;

    const int lrow  = tid >> 1;
    const int lhalf = tid & 1;
    const int kpb   = lhalf * 8;
    const unsigned* bhp = Wh + (size_t)(colBase + lrow) * Kp + kpb;
    const unsigned* blp = Wl + (size_t)(colBase + lrow) * Kp + kpb;

    float acc[2][4][4];
    #pragma unroll
    for (int i = 0; i < 2; i++)
        #pragma unroll
        for (int j = 0; j < 4; j++)
            #pragma unroll
            for (int r = 0; r < 4; r++) acc[i][j][r] = 0.f;

    const float4 fz = make_float4(0.f, 0.f, 0.f, 0.f);
    float4 ra[2]; uint4 rbh[2], rbl[2];
    ra[0] = av ? *(const float4*)ap       : fz;
    ra[1] = av ? *(const float4*)(ap + 4) : fz;
    rbh[0] = *(const uint4*)(bhp);     rbh[1] = *(const uint4*)(bhp + 4);
    rbl[0] = *(const uint4*)(blp);     rbl[1] = *(const uint4*)(blp + 4);

    constexpr int ntiles = K >> 5;
    #pragma unroll
    for (int kt = 0; kt < ntiles; kt++) {
        {
            unsigned h0, l0, h1, l1;
            split2(ra[0].x, ra[0].y, h0, l0);
            split2(ra[0].z, ra[0].w, h1, l1);
            Ah[arow][kpa+0] = h0;  Ah[arow][kpa+1] = h1;
            Al[arow][kpa+0] = l0;  Al[arow][kpa+1] = l1;
            split2(ra[1].x, ra[1].y, h0, l0);
            split2(ra[1].z, ra[1].w, h1, l1);
            Ah[arow][kpa+2] = h0;  Ah[arow][kpa+3] = h1;
            Al[arow][kpa+2] = l0;  Al[arow][kpa+3] = l1;
        }
        Bh[lrow][kpb+0] = rbh[0].x; Bh[lrow][kpb+1] = rbh[0].y;
        Bh[lrow][kpb+2] = rbh[0].z; Bh[lrow][kpb+3] = rbh[0].w;
        Bh[lrow][kpb+4] = rbh[1].x; Bh[lrow][kpb+5] = rbh[1].y;
        Bh[lrow][kpb+6] = rbh[1].z; Bh[lrow][kpb+7] = rbh[1].w;
        Bl[lrow][kpb+0] = rbl[0].x; Bl[lrow][kpb+1] = rbl[0].y;
        Bl[lrow][kpb+2] = rbl[0].z; Bl[lrow][kpb+3] = rbl[0].w;
        Bl[lrow][kpb+4] = rbl[1].x; Bl[lrow][kpb+5] = rbl[1].y;
        Bl[lrow][kpb+6] = rbl[1].z; Bl[lrow][kpb+7] = rbl[1].w;
        __syncthreads();

        if (kt + 1 < ntiles) {
            const int fo = (kt + 1) * 32;
            const int po = (kt + 1) * 16;
            ra[0] = av ? *(const float4*)(ap + fo)     : fz;
            ra[1] = av ? *(const float4*)(ap + fo + 4) : fz;
            rbh[0] = *(const uint4*)(bhp + po); rbh[1] = *(const uint4*)(bhp + po + 4);
            rbl[0] = *(const uint4*)(blp + po); rbl[1] = *(const uint4*)(blp + po + 4);
        }

        #pragma unroll
        for (int ks = 0; ks < 2; ks++) {
            const int kq = ks * 8 + tg;
            unsigned af[2][4], alf[2][4];
            #pragma unroll
            for (int mt = 0; mt < 2; mt++) {
                const int mm = m0 + mt * 16 + g;
                af[mt][0]  = Ah[mm][kq];   af[mt][1]  = Ah[mm+8][kq];
                af[mt][2]  = Ah[mm][kq+4]; af[mt][3]  = Ah[mm+8][kq+4];
                alf[mt][0] = Al[mm][kq];   alf[mt][1] = Al[mm+8][kq];
                alf[mt][2] = Al[mm][kq+4]; alf[mt][3] = Al[mm+8][kq+4];
            }
            #pragma unroll
            for (int nt = 0; nt < 4; nt++) {
                const int nn = n0 + nt * 8 + g;
                const unsigned bh0 = Bh[nn][kq], bh1 = Bh[nn][kq+4];
                const unsigned bl0 = Bl[nn][kq], bl1 = Bl[nn][kq+4];
                #pragma unroll
                for (int mt = 0; mt < 2; mt++) mma_bf16(acc[mt][nt], alf[mt], bh0, bh1);
                #pragma unroll
                for (int mt = 0; mt < 2; mt++) mma_bf16(acc[mt][nt], af[mt],  bl0, bl1);
                #pragma unroll
                for (int mt = 0; mt < 2; mt++) mma_bf16(acc[mt][nt], af[mt],  bh0, bh1);
            }
        }
        __syncthreads();
    }

    #pragma unroll
    for (int mt = 0; mt < 2; mt++) {
        const int m  = rowBase + m0 + mt * 16 + g;
        #pragma unroll
        for (int nt = 0; nt < 4; nt++) {
            const int n = colBase + n0 + nt * 8 + 2 * tg;
            const float2 bv = *(const float2*)&bias[n];
            float* c = acc[mt][nt];
            if (m < M) {
                *(float2*)&C[(size_t)m * N + n] = make_float2(c[0] + bv.x, c[1] + bv.y);
            }
            if (m + 8 < M) {
                *(float2*)&C[(size_t)(m + 8) * N + n] = make_float2(c[2] + bv.x, c[3] + bv.y);
            }
        }
    }
}

// ------------------------- tensor-core flash attention (q-tile 128; all single-bf16 MMA) -------------------------
// Block = (qtile 128, h, b), 256 threads; warp owns 16 q rows.
// Logits |s|~0.1 (LN-normalized x, 0.02-scale weights) => bf16 QK error ~4e-4 absolute,
// diluted by softmax + out-proj => end-to-end ~1e-4 (validated scaling from R16's PV-bf16 step).
__global__ __launch_bounds__(256)
void flash_attn_tc(const float* __restrict__ qkv, float* __restrict__ out) {
    const int qt = blockIdx.x, h = blockIdx.y, b = blockIdx.z;
    const int t = threadIdx.x, lane = t & 31, warp = t >> 5;
    const int g = lane >> 2, tg = lane & 3;

    __shared__ unsigned Qh[128][20];
    __shared__ unsigned Kh[64][20];
    __shared__ unsigned VTh[32][36];

    const int q0 = qt * 128;
    const size_t basebq = (size_t)b * CQ;
    const int r = t >> 1, half = t & 1;          // Q loader: 2 threads/row over 128 rows

    // ---- load Q tile (pre-scaled), bf16 pack ----
    {
        const int gq = q0 + r;
        float4 v[4];
        if (gq < CQ) {
            const float* p = qkv + (basebq + gq) * 768 + h * CDH + half * 16;
            #pragma unroll
            for (int j = 0; j < 4; j++) v[j] = *(const float4*)(p + 4*j);
        } else {
            #pragma unroll
            for (int j = 0; j < 4; j++) v[j] = make_float4(0.f,0.f,0.f,0.f);
        }
        #pragma unroll
        for (int j = 0; j < 4; j++) {
            Qh[r][half*8 + 2*j]     = pack_bf2(v[j].x * ATTN_SCALE, v[j].y * ATTN_SCALE);
            Qh[r][half*8 + 2*j + 1] = pack_bf2(v[j].z * ATTN_SCALE, v[j].w * ATTN_SCALE);
        }
    }
    __syncthreads();

    // Q fragments (persist across k-tiles); warp owns rows m0..m0+15
    unsigned qh[2][4];
    const int m0 = warp * 16;
    #pragma unroll
    for (int kc = 0; kc < 2; kc++) {
        const int kq = kc * 8 + tg;
        qh[kc][0] = Qh[m0+g][kq];   qh[kc][1] = Qh[m0+g+8][kq];
        qh[kc][2] = Qh[m0+g][kq+4]; qh[kc][3] = Qh[m0+g+8][kq+4];
    }

    float o[4][4];
    #pragma unroll
    for (int i = 0; i < 4; i++)
        #pragma unroll
        for (int j = 0; j < 4; j++) o[i][j] = 0.f;
    float m0r = -1e30f, m1r = -1e30f, l0r = 0.f, l1r = 0.f;

    // K/V loader mapping: 4 threads per key row (quarter-rows of 8 floats)
    const int vkey = t >> 2, vq = t & 3;

    for (int k0 = 0; k0 < CQ; k0 += 64) {
        __syncthreads();   // previous iteration's frag reads done

        // ---- load K quarter-row, bf16 pack ----
        {
            const int gk = k0 + vkey;
            float kf[8];
            if (gk < CQ) {
                const float* p = qkv + (basebq + gk) * 768 + CD + h * CDH + vq * 8;
                float4 a = *(const float4*)p;
                float4 c = *(const float4*)(p + 4);
                kf[0]=a.x; kf[1]=a.y; kf[2]=a.z; kf[3]=a.w;
                kf[4]=c.x; kf[5]=c.y; kf[6]=c.z; kf[7]=c.w;
            } else {
                #pragma unroll
                for (int j = 0; j < 8; j++) kf[j] = 0.f;
            }
            #pragma unroll
            for (int i = 0; i < 4; i++) {
                Kh[vkey][vq*4 + i] = pack_bf2(kf[2*i], kf[2*i+1]);
            }
        }

        // ---- load V quarter-row, transpose to [dim][keypair] via shfl(4) pairing (bf16) ----
        {
            const int gk = k0 + vkey;
            float vf[8];
            if (gk < CQ) {
                const float* p = qkv + (basebq + gk) * 768 + 2*CD + h * CDH + vq * 8;
                float4 a = *(const float4*)p;
                float4 c = *(const float4*)(p + 4);
                vf[0]=a.x; vf[1]=a.y; vf[2]=a.z; vf[3]=a.w;
                vf[4]=c.x; vf[5]=c.y; vf[6]=c.z; vf[7]=c.w;
            } else {
                #pragma unroll
                for (int j = 0; j < 8; j++) vf[j] = 0.f;
            }
            const int kp = vkey >> 1;
            #pragma unroll
            for (int j = 0; j < 8; j++) {
                float other = __shfl_xor_sync(0xffffffffu, vf[j], 4);
                if ((t & 4) == 0) {
                    VTh[vq*8 + j][kp] = pack_bf2(vf[j], other);
                }
            }
        }
        __syncthreads();

        // ---- scores S = Q K^T (bf16) ----
        float s[8][4];
        #pragma unroll
        for (int nt = 0; nt < 8; nt++)
            #pragma unroll
            for (int j = 0; j < 4; j++) s[nt][j] = 0.f;

        #pragma unroll
        for (int kc = 0; kc < 2; kc++) {
            const int kq = kc * 8 + tg;
            #pragma unroll
            for (int nt = 0; nt < 8; nt++) {
                const int nn = nt * 8 + g;
                const unsigned kh0 = Kh[nn][kq], kh1 = Kh[nn][kq+4];
                mma_bf16(s[nt], qh[kc], kh0, kh1);
            }
        }

        // ---- key-tail masking ----
        if (k0 + 64 > CQ) {
            #pragma unroll
            for (int nt = 0; nt < 8; nt++) {
                const int kk = k0 + nt * 8 + 2 * tg;
                if (kk     >= CQ) { s[nt][0] = -1e30f; s[nt][2] = -1e30f; }
                if (kk + 1 >= CQ) { s[nt][1] = -1e30f; s[nt][3] = -1e30f; }
            }
        }

        // ---- online softmax (rows g and g+8) ----
        float cm0 = -1e30f, cm1 = -1e30f;
        #pragma unroll
        for (int nt = 0; nt < 8; nt++) {
            cm0 = fmaxf(cm0, fmaxf(s[nt][0], s[nt][1]));
            cm1 = fmaxf(cm1, fmaxf(s[nt][2], s[nt][3]));
        }
        cm0 = fmaxf(cm0, __shfl_xor_sync(0xffffffffu, cm0, 1));
        cm0 = fmaxf(cm0, __shfl_xor_sync(0xffffffffu, cm0, 2));
        cm1 = fmaxf(cm1, __shfl_xor_sync(0xffffffffu, cm1, 1));
        cm1 = fmaxf(cm1, __shfl_xor_sync(0xffffffffu, cm1, 2));

        const float nm0 = fmaxf(m0r, cm0), nm1 = fmaxf(m1r, cm1);
        const float f0 = __expf(m0r - nm0), f1 = __expf(m1r - nm1);
        m0r = nm0; m1r = nm1;
        #pragma unroll
        for (int nt = 0; nt < 4; nt++) {
            o[nt][0] *= f0; o[nt][1] *= f0;
            o[nt][2] *= f1; o[nt][3] *= f1;
        }

        float ps0 = 0.f, ps1 = 0.f;
        #pragma unroll
        for (int kc = 0; kc < 4; kc++) {
            unsigned ph[4];
            #pragma unroll
            for (int e = 0; e < 2; e++) {
                const int nt = 2*kc + e;
                const float p0 = __expf(s[nt][0] - nm0);
                const float p1 = __expf(s[nt][1] - nm0);
                const float p2 = __expf(s[nt][2] - nm1);
                const float p3 = __expf(s[nt][3] - nm1);
                ps0 += p0 + p1; ps1 += p2 + p3;
                ph[2*e]   = pack_bf2(p0, p1);
                ph[2*e+1] = pack_bf2(p2, p3);
            }
            const int kq = kc * 8 + tg;
            #pragma unroll
            for (int ntd = 0; ntd < 4; ntd++) {
                const int nn = ntd * 8 + g;
                const unsigned vh0 = VTh[nn][kq], vh1 = VTh[nn][kq+4];
                mma_bf16(o[ntd], ph, vh0, vh1);
            }
        }
        ps0 += __shfl_xor_sync(0xffffffffu, ps0, 1);
        ps0 += __shfl_xor_sync(0xffffffffu, ps0, 2);
        ps1 += __shfl_xor_sync(0xffffffffu, ps1, 1);
        ps1 += __shfl_xor_sync(0xffffffffu, ps1, 2);
        l0r = l0r * f0 + ps0;
        l1r = l1r * f1 + ps1;
    }

    // ---- epilogue ----
    const float inv0 = 1.f / l0r, inv1 = 1.f / l1r;
    const int gq0 = q0 + m0 + g, gq1 = gq0 + 8;
    #pragma unroll
    for (int nt = 0; nt < 4; nt++) {
        const int d = h * CDH + nt * 8 + 2 * tg;
        if (gq0 < CQ)
            *(float2*)&out[(basebq + gq0) * CD + d] = make_float2(o[nt][0]*inv0, o[nt][1]*inv0);
        if (gq1 < CQ)
            *(float2*)&out[(basebq + gq1) * CD + d] = make_float2(o[nt][2]*inv1, o[nt][3]*inv1);
    }
}

// ------------------------- fused residual-add + LayerNorm (+ optional qpos-add) -------------------------
__global__ void add_ln_kernel(const float* __restrict__ a, const float* __restrict__ r,
                              const float* __restrict__ g, const float* __restrict__ be,
                              float* __restrict__ out, float* __restrict__ out2,
                              const float* __restrict__ qpos, float* __restrict__ xpq) {
    int row = blockIdx.x, t = threadIdx.x;   // 256 threads, D=256
    size_t idx = (size_t)row * CD + t;
    float v = a[idx] + r[idx];

    __shared__ float red[8];
    __shared__ float stat[2];

    float s = v;
    #pragma unroll
    for (int o = 16; o > 0; o >>= 1) s += __shfl_xor_sync(0xffffffffu, s, o);
    if ((t & 31) == 0) red[t >> 5] = s;
    __syncthreads();
    if (t == 0) {
        float tot = 0.f;
        #pragma unroll
        for (int i = 0; i < 8; i++) tot += red[i];
        stat[0] = tot * (1.f / CD);
    }
    __syncthreads();
    float mu = stat[0];
    float d = v - mu;
    float s2 = d * d;
    #pragma unroll
    for (int o = 16; o > 0; o >>= 1) s2 += __shfl_xor_sync(0xffffffffu, s2, o);
    if ((t & 31) == 0) red[t >> 5] = s2;
    __syncthreads();
    if (t == 0) {
        float tot = 0.f;
        #pragma unroll
        for (int i = 0; i < 8; i++) tot += red[i];
        stat[1] = tot * (1.f / CD);
    }
    __syncthreads();
    float o = d * rsqrtf(stat[1] + 1e-5f) * g[t] + be[t];
    out[idx] = o;
    if (out2) out2[idx] = o;
    if (qpos) xpq[idx] = o + qpos[idx];
}

// ------------------------- MSDA gather: one block per (b,q), warp = head -------------------------
__global__ void msda_kernel(const float* __restrict__ value, const float* __restrict__ offaw,
                            const float* __restrict__ refp,
                            const float* __restrict__ vr, float* __restrict__ out) {
    int bq = blockIdx.x;
    int b = bq / CQ;
    int t = threadIdx.x;          // 256 threads = 8 warps
    int h = t >> 5, lane = t & 31;

    float logit = (lane < 16) ? offaw[(size_t)bq * 384 + 256 + h * 16 + lane] : -1e30f;
    float m = logit;
    #pragma unroll
    for (int o = 8; o > 0; o >>= 1) m = fmaxf(m, __shfl_xor_sync(0xffffffffu, m, o, 16));
    float e = (lane < 16) ? __expf(logit - m) : 0.f;
    float es = e;
    #pragma unroll
    for (int o = 8; o > 0; o >>= 1) es += __shfl_xor_sync(0xffffffffu, es, o, 16);
    float p = e / es;

    float rx = refp[(size_t)bq * 2 + 0];
    float ry = refp[(size_t)bq * 2 + 1];

    const int   Ws[4] = {100, 50, 25, 13};
    const int   Hs[4] = {100, 50, 25, 13};
    const int   ST[4] = {0, 10000, 12500, 13125};

    const float* voff = value + (size_t)b * CS * CD + h * CDH + lane;
    float acc = 0.f;

    #pragma unroll
    for (int l = 0; l < 4; l++) {
        int W_ = Ws[l], H_ = Hs[l], st = ST[l];
        float vrx = vr[b * 8 + l * 2 + 0];
        float vry = vr[b * 8 + l * 2 + 1];
        float bx = rx * vrx * (float)W_ - 0.5f;
        float by = ry * vry * (float)H_ - 0.5f;
        #pragma unroll
        for (int pp = 0; pp < 4; pp++) {
            size_t oidx = (size_t)bq * 384 + (size_t)(((h * 4 + l) * 4 + pp) * 2);
            float x = bx + offaw[oidx + 0];
            float y = by + offaw[oidx + 1];
            float w = __shfl_sync(0xffffffffu, p, l * 4 + pp, 32);
            float x0f = floorf(x), y0f = floorf(y);
            float wx = x - x0f, wy = y - y0f;
            int x0 = (int)x0f, y0 = (int)y0f;

            float gsum = 0.f;
            {
                int xi = x0, yi = y0;
                if (xi >= 0 && xi < W_ && yi >= 0 && yi < H_)
                    gsum = fmaf(voff[(size_t)(st + yi * W_ + xi) * CD], (1.f - wx) * (1.f - wy), gsum);
            }
            {
                int xi = x0 + 1, yi = y0;
                if (xi >= 0 && xi < W_ && yi >= 0 && yi < H_)
                    gsum = fmaf(voff[(size_t)(st + yi * W_ + xi) * CD], wx * (1.f - wy), gsum);
            }
            {
                int xi = x0, yi = y0 + 1;
                if (xi >= 0 && xi < W_ && yi >= 0 && yi < H_)
                    gsum = fmaf(voff[(size_t)(st + yi * W_ + xi) * CD], (1.f - wx) * wy, gsum);
            }
            {
                int xi = x0 + 1, yi = y0 + 1;
                if (xi >= 0 && xi < W_ && yi >= 0 && yi < H_)
                    gsum = fmaf(voff[(size_t)(st + yi * W_ + xi) * CD], wx * wy, gsum);
            }
            acc = fmaf(w, gsum, acc);
        }
    }
    out[(size_t)bq * CD + h * CDH + lane] = acc;
}

// ------------------------- driver -------------------------
extern "C" void kernel_launch(void* const* d_in, const int* in_sizes, int n_in,
                              void* d_out, int out_size) {
    const float* tgt      = (const float*)d_in[0];
    const float* refp     = (const float*)d_in[1];
    const float* memory   = (const float*)d_in[2];
    const float* vratios  = (const float*)d_in[5];
    const float* qpos     = (const float*)d_in[6];
    const float* sa_in_w  = (const float*)d_in[7];
    const float* sa_in_b  = (const float*)d_in[8];
    const float* sa_out_w = (const float*)d_in[9];
    const float* sa_out_b = (const float*)d_in[10];
    const float* n1_g     = (const float*)d_in[11];
    const float* n1_b     = (const float*)d_in[12];
    const float* n2_g     = (const float*)d_in[13];
    const float* n2_b     = (const float*)d_in[14];
    const float* n3_g     = (const float*)d_in[15];
    const float* n3_b     = (const float*)d_in[16];
    const float* vp_w     = (const float*)d_in[17];
    const float* vp_b     = (const float*)d_in[18];
    const float* so_w     = (const float*)d_in[19];
    const float* so_b     = (const float*)d_in[20];
    const float* aw_w     = (const float*)d_in[21];
    const float* aw_b     = (const float*)d_in[22];
    const float* op_w     = (const float*)d_in[23];
    const float* op_b     = (const float*)d_in[24];
    const float* ff1_w    = (const float*)d_in[25];
    const float* ff1_b    = (const float*)d_in[26];
    const float* ff2_w    = (const float*)d_in[27];
    const float* ff2_b    = (const float*)d_in[28];

    float *value, *x, *xpq, *qkv, *attn, *t2, *offaw, *ms, *ffh, *sob;
    unsigned *wh, *wl;
    cudaGetSymbolAddress((void**)&value, g_value);
    cudaGetSymbolAddress((void**)&x,     g_x);
    cudaGetSymbolAddress((void**)&xpq,   g_xpq);
    cudaGetSymbolAddress((void**)&qkv,   g_qkv);
    cudaGetSymbolAddress((void**)&attn,  g_attn);
    cudaGetSymbolAddress((void**)&t2,    g_t2);
    cudaGetSymbolAddress((void**)&offaw, g_offaw);
    cudaGetSymbolAddress((void**)&ms,    g_ms);
    cudaGetSymbolAddress((void**)&ffh,   g_ffh);
    cudaGetSymbolAddress((void**)&sob,   g_sob);
    cudaGetSymbolAddress((void**)&wh,    g_wh);
    cudaGetSymbolAddress((void**)&wl,    g_wl);

    float* out = (float*)d_out;

    // single fused prologue kernel (splits, xpq, refs, sob) + state memcpy
    cudaMemcpyAsync(x, tgt, sizeof(float) * CBQ * CD, cudaMemcpyDeviceToDevice, 0);
    prologue_kernel<<<(PRO_TOTAL + 255)/256, 256>>>(
        vp_w, sa_in_w, sa_out_w, so_w, aw_w, op_w, ff1_w, ff2_w, wh, wl,
        tgt, qpos, xpq,
        refp, out + (size_t)CNLAYERS * CBQ * CD,
        so_b, aw_b, sob);

    // layer-invariant value projection (computed ONCE)
    gemm_bf3<false, 256><<<dim3(CD/128, (CBS + 127)/128), 256>>>(
        memory, wh + OFF_VP, wl + OFF_VP, vp_b, value, CBS, CD);

    const int MB  = (CBQ + 127) / 128;  // 57 row-blocks (128-row tiles)
    const int MB2 = (CBQ + 63) / 64;    // 113 row-blocks (64-row tiles)

    for (int L = 0; L < CNLAYERS; L++) {
        // ---- MHA ----
        gemm_bf3<false, 256><<<dim3(768/128, MB), 256>>>(
            xpq, wh + OFF_SAIN, wl + OFF_SAIN, sa_in_b, qkv, CBQ, 3*CD);
        flash_attn_tc<<<dim3((CQ + 127)/128, CNH, CB), 256>>>(qkv, attn);
        gemm_bf3_m64<256><<<dim3(CD/128, MB2), 256>>>(
            attn, wh + OFF_SAOU, wl + OFF_SAOU, sa_out_b, t2, CBQ, CD);
        add_ln_kernel<<<CBQ, CD>>>(xpq, t2, n1_g, n1_b, x, nullptr, nullptr, nullptr);

        // ---- MSDA ----
        gemm_bf3_m64<256><<<dim3(384/128, MB2), 256>>>(
            x, wh + OFF_SO, wl + OFF_SO, sob, offaw, CBQ, 384);
        msda_kernel<<<CBQ, 256>>>(value, offaw, refp, vratios, ms);
        gemm_bf3_m64<256><<<dim3(CD/128, MB2), 256>>>(
            ms, wh + OFF_OP, wl + OFF_OP, op_b, t2, CBQ, CD);
        add_ln_kernel<<<CBQ, CD>>>(x, t2, n2_g, n2_b, x, nullptr, nullptr, nullptr);

        // ---- FFN ----
        gemm_bf3<true, 256><<<dim3(CFF/128, MB), 256>>>(
            x, wh + OFF_FF1, wl + OFF_FF1, ff1_b, ffh, CBQ, CFF);
        gemm_bf3_m64<1024><<<dim3(CD/128, MB2), 256>>>(
            ffh, wh + OFF_FF2, wl + OFF_FF2, ff2_b, t2, CBQ, CD);
        // fused: x = LN(x + t2); out[L] = x; xpq = x + qpos (for next layer)
        add_ln_kernel<<<CBQ, CD>>>(x, t2, n3_g, n3_b, x, out + (size_t)L * CBQ * CD, qpos, xpq);
    }
}